// round 6
// baseline (speedup 1.0000x reference)
#include <cuda_runtime.h>
#include <math.h>

#define T_STEPS 2048
#define BATCH   16
#define DM      1024
#define DB      128
#define DH      512
#define ROWS    (T_STEPS*BATCH)   /* 32768 */
#define EPSLN   1e-5f

// ---------------- scratch (no allocations allowed; static device globals) ---
__device__ float g_H[ROWS*DB];      // bottleneck pre-activation  h = x@Wb+bb
__device__ float g_Wpre[ROWS*DB];   // tanh(h@Ww+bw)
__device__ float g_Mem[ROWS*DB];    // mem state entering step t  (t*2048 + b*128 + d)
__device__ float g_h1[ROWS*DB];     // after memory LN
__device__ float g_hid[ROWS*DH];    // relu(h1@ff1+b1)
__device__ float g_h2[ROWS*DB];     // after ff LN

// ============================================================================
// Generic SGEMM, BM=64, BN=128, BK=32, 256 threads, 8x4 micro-tile.
// EPI: 0 = +bias, 1 = +bias,tanh, 2 = +bias,relu,
//      3 = +bias,+res, then LayerNorm over the 128-wide row (n0 must be 0)
// ============================================================================
template<int KTOT, int EPI>
__global__ void __launch_bounds__(256)
gemm_bn128(const float* __restrict__ A, int lda,
           const float* __restrict__ Bw, int ldb,
           const float* __restrict__ bias,
           const float* __restrict__ res,
           const float* __restrict__ ln_s, const float* __restrict__ ln_b,
           float* __restrict__ C, int ldc)
{
    __shared__ float As[32][64];    // k-major (transposed)
    __shared__ float Bs[32][128];

    const int tid = threadIdx.x;
    const int m0  = blockIdx.y * 64;
    const int n0  = blockIdx.x * 128;
    const int tx  = tid & 31;       // 32 col-threads (4 cols each)
    const int ty  = tid >> 5;       // 8 row-groups (8 rows each)

    float acc[8][4];
#pragma unroll
    for (int i = 0; i < 8; i++)
#pragma unroll
        for (int j = 0; j < 4; j++) acc[i][j] = 0.f;

    for (int k0 = 0; k0 < KTOT; k0 += 32) {
        // ---- load A tile (transpose into As[k][m]) -------------------------
#pragma unroll
        for (int it = 0; it < 2; ++it) {
            int idx = tid + it * 256;           // 0..511
            int m   = idx >> 3;                 // 0..63
            int kv  = idx & 7;                  // float4 slot in 32-wide K
            float4 v = *(const float4*)&A[(size_t)(m0 + m) * lda + k0 + kv * 4];
            As[kv*4+0][m] = v.x; As[kv*4+1][m] = v.y;
            As[kv*4+2][m] = v.z; As[kv*4+3][m] = v.w;
        }
        // ---- load B tile ---------------------------------------------------
#pragma unroll
        for (int it = 0; it < 4; ++it) {
            int idx = tid + it * 256;           // 0..1023 float4s
            int k   = idx >> 5;                 // 0..31
            int nv  = idx & 31;                 // 0..31 float4 cols
            *(float4*)&Bs[k][nv*4] =
                *(const float4*)&Bw[(size_t)(k0 + k) * ldb + n0 + nv * 4];
        }
        __syncthreads();
        // ---- compute -------------------------------------------------------
#pragma unroll
        for (int k = 0; k < 32; k++) {
            float4 b = *(const float4*)&Bs[k][tx*4];
#pragma unroll
            for (int i = 0; i < 8; i++) {
                float a = As[k][ty*8 + i];
                acc[i][0] += a * b.x; acc[i][1] += a * b.y;
                acc[i][2] += a * b.z; acc[i][3] += a * b.w;
            }
        }
        __syncthreads();
    }

    // ---- epilogue ----------------------------------------------------------
    const float4 bias4 = *(const float4*)&bias[n0 + tx*4];

    if (EPI == 3) {
        const float4 s4 = *(const float4*)&ln_s[tx*4];
        const float4 b4 = *(const float4*)&ln_b[tx*4];
#pragma unroll
        for (int i = 0; i < 8; i++) {
            int r = m0 + ty*8 + i;
            float4 rv = *(const float4*)&res[(size_t)r * 128 + tx*4];
            float v0 = acc[i][0] + bias4.x + rv.x;
            float v1 = acc[i][1] + bias4.y + rv.y;
            float v2 = acc[i][2] + bias4.z + rv.z;
            float v3 = acc[i][3] + bias4.w + rv.w;
            float s  = v0 + v1 + v2 + v3;
            float ss = v0*v0 + v1*v1 + v2*v2 + v3*v3;
#pragma unroll
            for (int o = 16; o > 0; o >>= 1) {
                s  += __shfl_xor_sync(0xffffffffu, s,  o);
                ss += __shfl_xor_sync(0xffffffffu, ss, o);
            }
            float mu  = s  * (1.f/128.f);
            float var = ss * (1.f/128.f) - mu*mu;
            float rs  = rsqrtf(var + EPSLN);
            float4 o4;
            o4.x = (v0 - mu) * rs * s4.x + b4.x;
            o4.y = (v1 - mu) * rs * s4.y + b4.y;
            o4.z = (v2 - mu) * rs * s4.z + b4.z;
            o4.w = (v3 - mu) * rs * s4.w + b4.w;
            *(float4*)&C[(size_t)r * ldc + tx*4] = o4;
        }
    } else {
#pragma unroll
        for (int i = 0; i < 8; i++) {
            int r = m0 + ty*8 + i;
            float4 o4;
            o4.x = acc[i][0] + bias4.x; o4.y = acc[i][1] + bias4.y;
            o4.z = acc[i][2] + bias4.z; o4.w = acc[i][3] + bias4.w;
            if (EPI == 1) {
                o4.x = tanhf(o4.x); o4.y = tanhf(o4.y);
                o4.z = tanhf(o4.z); o4.w = tanhf(o4.w);
            }
            if (EPI == 2) {
                o4.x = fmaxf(o4.x, 0.f); o4.y = fmaxf(o4.y, 0.f);
                o4.z = fmaxf(o4.z, 0.f); o4.w = fmaxf(o4.w, 0.f);
            }
            *(float4*)&C[(size_t)r * ldc + n0 + tx*4] = o4;
        }
    }
}

// ============================================================================
// Elementwise gated-decay scan. 2048 independent (b,d) lanes, T steps each.
// Stores mem state *entering* each step t; final state -> out tail.
// ============================================================================
__global__ void scan_kernel(const float* __restrict__ Wpre,
                            const unsigned char* __restrict__ mask,
                            const float* __restrict__ mem0,
                            const float* __restrict__ decay_logit,
                            float* __restrict__ Mem,
                            float* __restrict__ out_final)
{
    int i = blockIdx.x * blockDim.x + threadIdx.x;   // 0..2047
    if (i >= BATCH * DB) return;
    int b = i >> 7;
    float dec = 1.f / (1.f + expf(-decay_logit[i & 127]));
    float omd = 1.f - dec;
    float m   = mem0[i];
#pragma unroll 4
    for (int t = 0; t < T_STEPS; t++) {
        Mem[(size_t)t * 2048 + i] = m;
        float w  = Wpre[(size_t)t * 2048 + i];
        float nm = dec * m + omd * w;
        m = mask[t * BATCH + b] ? m : nm;
    }
    out_final[i] = m;
}

// ============================================================================
// Unbottleneck + output LayerNorm, fused:
// out = LN(x + h2@Wu + bu).  BM=16 rows, BN=1024 (full d_model), BK=8.
// 8 warps; each warp owns 2 full rows -> LN is a pure warp shuffle reduce.
// ============================================================================
__global__ void __launch_bounds__(256)
gemm_wu_oln(const float* __restrict__ A,      // g_h2 [ROWS][128]
            const float* __restrict__ Wu,     // [128][1024]
            const float* __restrict__ bu,     // [1024]
            const float* __restrict__ x,      // [ROWS][1024]
            const float* __restrict__ lns,    // oln_s
            const float* __restrict__ lnb,    // oln_b
            float* __restrict__ out)          // [ROWS][1024]
{
    __shared__ float  As[8][16];
    __shared__ float4 Bs[8][256];             // 8 k x 1024 cols (as float4)

    const int tid  = threadIdx.x;
    const int lane = tid & 31;
    const int w    = tid >> 5;                // warp id 0..7
    const int m0   = blockIdx.x * 16;

    float4 acc[2][8];
#pragma unroll
    for (int r = 0; r < 2; r++)
#pragma unroll
        for (int c = 0; c < 8; c++) acc[r][c] = make_float4(0.f,0.f,0.f,0.f);

    for (int k0 = 0; k0 < 128; k0 += 8) {
        if (tid < 128) {
            int m = tid >> 3, k = tid & 7;
            As[k][m] = A[(size_t)(m0 + m) * 128 + k0 + k];
        }
#pragma unroll
        for (int it = 0; it < 8; ++it) {
            int vec = tid + it * 256;         // 0..2047 float4s
            int k   = vec >> 8;               // 0..7
            int n4  = vec & 255;              // 0..255
            Bs[k][n4] = *(const float4*)&Wu[(size_t)(k0 + k) * 1024 + n4 * 4];
        }
        __syncthreads();
#pragma unroll
        for (int k = 0; k < 8; k++) {
            float a0 = As[k][w*2 + 0];
            float a1 = As[k][w*2 + 1];
#pragma unroll
            for (int c = 0; c < 8; c++) {
                float4 bv = Bs[k][c*32 + lane];
                acc[0][c].x += a0*bv.x; acc[0][c].y += a0*bv.y;
                acc[0][c].z += a0*bv.z; acc[0][c].w += a0*bv.w;
                acc[1][c].x += a1*bv.x; acc[1][c].y += a1*bv.y;
                acc[1][c].z += a1*bv.z; acc[1][c].w += a1*bv.w;
            }
        }
        __syncthreads();
    }

    // epilogue: +bu, +x, LayerNorm over 1024 (warp owns full row), scale/bias
#pragma unroll
    for (int ri = 0; ri < 2; ++ri) {
        int r = m0 + w*2 + ri;
        float4 vals[8];
        float s = 0.f, ss = 0.f;
#pragma unroll
        for (int c = 0; c < 8; c++) {
            int n = (c*32 + lane) * 4;
            float4 b4 = *(const float4*)&bu[n];
            float4 x4 = *(const float4*)&x[(size_t)r * 1024 + n];
            float4 v;
            v.x = acc[ri][c].x + b4.x + x4.x;
            v.y = acc[ri][c].y + b4.y + x4.y;
            v.z = acc[ri][c].z + b4.z + x4.z;
            v.w = acc[ri][c].w + b4.w + x4.w;
            vals[c] = v;
            s  += v.x + v.y + v.z + v.w;
            ss += v.x*v.x + v.y*v.y + v.z*v.z + v.w*v.w;
        }
#pragma unroll
        for (int o = 16; o > 0; o >>= 1) {
            s  += __shfl_xor_sync(0xffffffffu, s,  o);
            ss += __shfl_xor_sync(0xffffffffu, ss, o);
        }
        float mu  = s  * (1.f/1024.f);
        float var = ss * (1.f/1024.f) - mu*mu;
        float rs  = rsqrtf(var + EPSLN);
#pragma unroll
        for (int c = 0; c < 8; c++) {
            int n = (c*32 + lane) * 4;
            float4 s4 = *(const float4*)&lns[n];
            float4 b4 = *(const float4*)&lnb[n];
            float4 o4;
            o4.x = (vals[c].x - mu) * rs * s4.x + b4.x;
            o4.y = (vals[c].y - mu) * rs * s4.y + b4.y;
            o4.z = (vals[c].z - mu) * rs * s4.z + b4.z;
            o4.w = (vals[c].w - mu) * rs * s4.w + b4.w;
            *(float4*)&out[(size_t)r * 1024 + n] = o4;
        }
    }
}

// ============================================================================
extern "C" void kernel_launch(void* const* d_in, const int* in_sizes, int n_in,
                              void* d_out, int out_size)
{
    const float*         x     = (const float*)d_in[0];
    const unsigned char* mask  = (const unsigned char*)d_in[1];
    const float*         mem0  = (const float*)d_in[2];
    const float*         Wb    = (const float*)d_in[3];
    const float*         bb    = (const float*)d_in[4];
    const float*         Wu    = (const float*)d_in[5];
    const float*         bu    = (const float*)d_in[6];
    const float*         Wr    = (const float*)d_in[7];
    const float*         br    = (const float*)d_in[8];
    const float*         Ww    = (const float*)d_in[9];
    const float*         bw    = (const float*)d_in[10];
    const float*         dlg   = (const float*)d_in[11];
    const float*         ffw1  = (const float*)d_in[12];
    const float*         ffb1  = (const float*)d_in[13];
    const float*         ffw2  = (const float*)d_in[14];
    const float*         ffb2  = (const float*)d_in[15];
    const float*         mlns  = (const float*)d_in[16];
    const float*         mlnb  = (const float*)d_in[17];
    const float*         flns  = (const float*)d_in[18];
    const float*         flnb  = (const float*)d_in[19];
    const float*         olns  = (const float*)d_in[20];
    const float*         olnb  = (const float*)d_in[21];
    float* out = (float*)d_out;

    float *H, *Wpre, *Mem, *h1, *hid, *h2;
    cudaGetSymbolAddress((void**)&H,    g_H);
    cudaGetSymbolAddress((void**)&Wpre, g_Wpre);
    cudaGetSymbolAddress((void**)&Mem,  g_Mem);
    cudaGetSymbolAddress((void**)&h1,   g_h1);
    cudaGetSymbolAddress((void**)&hid,  g_hid);
    cudaGetSymbolAddress((void**)&h2,   g_h2);

    dim3 blk(256);

    // 1) H = x @ Wb + bb                   (M=32768, K=1024, N=128)
    gemm_bn128<1024,0><<<dim3(1,512), blk>>>(x, 1024, Wb, 128, bb,
                                             nullptr, nullptr, nullptr, H, 128);
    // 2) Wpre = tanh(H @ Ww + bw)          (K=128, N=128)
    gemm_bn128<128,1><<<dim3(1,512), blk>>>(H, 128, Ww, 128, bw,
                                            nullptr, nullptr, nullptr, Wpre, 128);
    // 3) elementwise gated-decay scan -> Mem[t], final mem -> out tail
    scan_kernel<<<8, 256>>>(Wpre, mask, mem0, dlg, Mem,
                            out + (size_t)ROWS * DM);
    // 4) h1 = LN(H + Mem@Wr + br) * mln_s + mln_b
    gemm_bn128<128,3><<<dim3(1,512), blk>>>(Mem, 128, Wr, 128, br,
                                            H, mlns, mlnb, h1, 128);
    // 5) hid = relu(h1 @ ff_w1 + ff_b1)    (N=512)
    gemm_bn128<128,2><<<dim3(4,512), blk>>>(h1, 128, ffw1, 512, ffb1,
                                            nullptr, nullptr, nullptr, hid, 512);
    // 6) h2 = LN(h1 + hid@ff_w2 + ff_b2) * fln_s + fln_b   (K=512)
    gemm_bn128<512,3><<<dim3(1,512), blk>>>(hid, 512, ffw2, 128, ffb2,
                                            h1, flns, flnb, h2, 128);
    // 7) out = LN(x + h2@Wu + bu) * oln_s + oln_b          (N=1024, fused)
    gemm_wu_oln<<<2048, blk>>>(h2, Wu, bu, x, olns, olnb, out);

    (void)in_sizes; (void)n_in; (void)out_size;
}

// round 10
// speedup vs baseline: 1.5682x; 1.5682x over previous
#include <cuda_runtime.h>
#include <math.h>
#include <stdint.h>

#define T_STEPS 2048
#define BATCH   16
#define DM      1024
#define DB      128
#define DH      512
#define ROWS    (T_STEPS*BATCH)   /* 32768 */
#define EPSLN   1e-5f

// ---------------- scratch (no allocations allowed; static device globals) ---
__device__ float g_H[ROWS*DB];      // bottleneck pre-activation  h = x@Wb+bb
__device__ float g_Wpre[ROWS*DB];   // tanh(h@Ww+bw)
__device__ float g_Mem[ROWS*DB];    // mem state entering step t
__device__ float g_h1[ROWS*DB];     // after memory LN
__device__ float g_hid[ROWS*DH];    // relu(h1@ff1+b1)
__device__ float g_h2[ROWS*DB];     // after ff LN
__device__ float g_up[ROWS*DM];     // h2@Wu + bu (pre output-LN)

// ---------------------------------------------------------------------------
__device__ __forceinline__ uint32_t f2tf32(float f) {
    uint32_t r;
    asm("cvt.rna.tf32.f32 %0, %1;" : "=r"(r) : "f"(f));
    return r;
}

__device__ __forceinline__ void mma8(float& d0, float& d1, float& d2, float& d3,
                                     uint32_t a0, uint32_t a1, uint32_t a2, uint32_t a3,
                                     uint32_t b0, uint32_t b1)
{
    asm volatile(
        "mma.sync.aligned.m16n8k8.row.col.f32.tf32.tf32.f32 "
        "{%0,%1,%2,%3}, {%4,%5,%6,%7}, {%8,%9}, {%0,%1,%2,%3};"
        : "+f"(d0), "+f"(d1), "+f"(d2), "+f"(d3)
        : "r"(a0), "r"(a1), "r"(a2), "r"(a3), "r"(b0), "r"(b1));
}

// ============================================================================
// tf32 tensor-core GEMM: C[M,N] = A[M,K] @ B[K,N], block tile 128x128x32,
// 256 threads = 8 warps in 2(m) x 4(n), warp tile 64x32, mma m16n8k8.
// A staged as [m][k-perm] tf32 (frag = LDS.64), B staged as [k][n] tf32.
// EPI: 0 = +bias, 1 = +bias,tanh, 2 = +bias,relu,
//      3 = +bias,+res, then LayerNorm over the 128-wide row (needs n0==0)
// ============================================================================
template<int KTOT, int EPI>
__global__ void __launch_bounds__(256)
mma_gemm(const float* __restrict__ A, int lda,
         const float* __restrict__ Bw, int ldb,
         const float* __restrict__ bias,
         const float* __restrict__ res,
         const float* __restrict__ ln_s, const float* __restrict__ ln_b,
         float* __restrict__ C, int ldc)
{
    __shared__ uint32_t As[128][34];    // [m][k-perm], stride 34 keeps uint2 aligned
    __shared__ uint32_t Bs[32][132];    // [k][n]
    __shared__ float red_s[4][128];     // EPI3 per-(wcol,row) partial sums
    __shared__ float red_ss[4][128];

    const int tid  = threadIdx.x;
    const int lane = tid & 31;
    const int wid  = tid >> 5;
    const int g    = lane >> 2;         // 0..7
    const int t    = lane & 3;          // 0..3
    const int wrow = wid >> 2;          // 0..1 -> m offset 64
    const int wcol = wid & 3;           // 0..3 -> n offset 32
    const int wm   = wrow * 64;
    const int wn   = wcol * 32;
    const int m0   = blockIdx.y * 128;
    const int n0   = blockIdx.x * 128;

    float acc[4][4][4];                 // [mi][ni][reg]
#pragma unroll
    for (int mi = 0; mi < 4; mi++)
#pragma unroll
        for (int ni = 0; ni < 4; ni++)
#pragma unroll
            for (int r = 0; r < 4; r++) acc[mi][ni][r] = 0.f;

    for (int k0 = 0; k0 < KTOT; k0 += 32) {
        // ---- stage A: 128 x 32 floats -> tf32, k-permuted within 8-groups --
#pragma unroll
        for (int it = 0; it < 4; ++it) {
            int idx = tid + it * 256;           // 0..1023 float4s
            int m   = idx >> 3;                 // 0..127
            int kv  = idx & 7;                  // float4 slot
            float4 v = *(const float4*)&A[(size_t)(m0 + m) * lda + k0 + kv * 4];
            float vv[4] = {v.x, v.y, v.z, v.w};
#pragma unroll
            for (int j = 0; j < 4; j++) {
                int kk  = kv * 4 + j;           // 0..31
                int grp = kk >> 3;
                int kb  = kk & 7;
                int kp  = grp * 8 + ((kb & 3) * 2) + (kb >> 2);
                As[m][kp] = f2tf32(vv[j]);
            }
        }
        // ---- stage B: 32 x 128 floats -> tf32, direct [k][n] ---------------
#pragma unroll
        for (int it = 0; it < 4; ++it) {
            int idx = tid + it * 256;           // 0..1023 float4s
            int k   = idx >> 5;                 // 0..31
            int nv  = idx & 31;
            float4 v = *(const float4*)&Bw[(size_t)(k0 + k) * ldb + n0 + nv * 4];
            Bs[k][nv*4+0] = f2tf32(v.x);
            Bs[k][nv*4+1] = f2tf32(v.y);
            Bs[k][nv*4+2] = f2tf32(v.z);
            Bs[k][nv*4+3] = f2tf32(v.w);
        }
        __syncthreads();

        // ---- compute: 4 k-fragments of 8 -----------------------------------
#pragma unroll
        for (int kk = 0; kk < 4; kk++) {
            uint2 aF0[4], aF1[4];               // (a0,a2) / (a1,a3)
#pragma unroll
            for (int mi = 0; mi < 4; mi++) {
                aF0[mi] = *(const uint2*)&As[wm + mi*16 + g    ][kk*8 + 2*t];
                aF1[mi] = *(const uint2*)&As[wm + mi*16 + g + 8][kk*8 + 2*t];
            }
            uint32_t bF0[4], bF1[4];
#pragma unroll
            for (int ni = 0; ni < 4; ni++) {
                bF0[ni] = Bs[kk*8 + t    ][wn + ni*8 + g];
                bF1[ni] = Bs[kk*8 + t + 4][wn + ni*8 + g];
            }
#pragma unroll
            for (int mi = 0; mi < 4; mi++)
#pragma unroll
                for (int ni = 0; ni < 4; ni++)
                    mma8(acc[mi][ni][0], acc[mi][ni][1], acc[mi][ni][2], acc[mi][ni][3],
                         aF0[mi].x, aF1[mi].x, aF0[mi].y, aF1[mi].y,
                         bF0[ni], bF1[ni]);
        }
        __syncthreads();
    }

    // ---- epilogue ----------------------------------------------------------
    // thread's columns: c = n0 + wn + ni*8 + 2*t (+1);  rows: m0+wm+mi*16+g (+8)
    float2 bias2[4];
#pragma unroll
    for (int ni = 0; ni < 4; ni++)
        bias2[ni] = *(const float2*)&bias[n0 + wn + ni*8 + 2*t];

    if (EPI != 3) {
#pragma unroll
        for (int mi = 0; mi < 4; mi++) {
            size_t r0 = (size_t)(m0 + wm + mi*16 + g);
            size_t r1 = r0 + 8;
#pragma unroll
            for (int ni = 0; ni < 4; ni++) {
                int c = n0 + wn + ni*8 + 2*t;
                float v0 = acc[mi][ni][0] + bias2[ni].x;
                float v1 = acc[mi][ni][1] + bias2[ni].y;
                float v2 = acc[mi][ni][2] + bias2[ni].x;
                float v3 = acc[mi][ni][3] + bias2[ni].y;
                if (EPI == 1) { v0 = tanhf(v0); v1 = tanhf(v1); v2 = tanhf(v2); v3 = tanhf(v3); }
                if (EPI == 2) {
                    v0 = fmaxf(v0, 0.f); v1 = fmaxf(v1, 0.f);
                    v2 = fmaxf(v2, 0.f); v3 = fmaxf(v3, 0.f);
                }
                *(float2*)&C[r0 * ldc + c] = make_float2(v0, v1);
                *(float2*)&C[r1 * ldc + c] = make_float2(v2, v3);
            }
        }
    } else {
        // v = acc + bias + res; LayerNorm across the 128 cols of each row.
#pragma unroll
        for (int mi = 0; mi < 4; mi++) {
            size_t r0 = (size_t)(m0 + wm + mi*16 + g);
            size_t r1 = r0 + 8;
#pragma unroll
            for (int ni = 0; ni < 4; ni++) {
                int c = wn + ni*8 + 2*t;
                float2 rv0 = *(const float2*)&res[r0 * 128 + c];
                float2 rv1 = *(const float2*)&res[r1 * 128 + c];
                acc[mi][ni][0] += bias2[ni].x + rv0.x;
                acc[mi][ni][1] += bias2[ni].y + rv0.y;
                acc[mi][ni][2] += bias2[ni].x + rv1.x;
                acc[mi][ni][3] += bias2[ni].y + rv1.y;
            }
        }
        // per-thread partials for its two row-sets, quad(shuffle)-reduced
#pragma unroll
        for (int mi = 0; mi < 4; mi++) {
            float s0 = 0.f, ss0 = 0.f, s1 = 0.f, ss1 = 0.f;
#pragma unroll
            for (int ni = 0; ni < 4; ni++) {
                float a0 = acc[mi][ni][0], a1 = acc[mi][ni][1];
                float a2 = acc[mi][ni][2], a3 = acc[mi][ni][3];
                s0 += a0 + a1;  ss0 += a0*a0 + a1*a1;
                s1 += a2 + a3;  ss1 += a2*a2 + a3*a3;
            }
#pragma unroll
            for (int o = 1; o <= 2; o <<= 1) {
                s0  += __shfl_xor_sync(0xffffffffu, s0,  o);
                ss0 += __shfl_xor_sync(0xffffffffu, ss0, o);
                s1  += __shfl_xor_sync(0xffffffffu, s1,  o);
                ss1 += __shfl_xor_sync(0xffffffffu, ss1, o);
            }
            if (t == 0) {
                int rb0 = wm + mi*16 + g;
                red_s [wcol][rb0]     = s0;  red_ss[wcol][rb0]     = ss0;
                red_s [wcol][rb0 + 8] = s1;  red_ss[wcol][rb0 + 8] = ss1;
            }
        }
        __syncthreads();

        float2 ls2[4], lb2[4];
#pragma unroll
        for (int ni = 0; ni < 4; ni++) {
            ls2[ni] = *(const float2*)&ln_s[wn + ni*8 + 2*t];
            lb2[ni] = *(const float2*)&ln_b[wn + ni*8 + 2*t];
        }
#pragma unroll
        for (int mi = 0; mi < 4; mi++) {
            int rb0 = wm + mi*16 + g;
            int rb1 = rb0 + 8;
            float S0  = red_s [0][rb0] + red_s [1][rb0] + red_s [2][rb0] + red_s [3][rb0];
            float SS0 = red_ss[0][rb0] + red_ss[1][rb0] + red_ss[2][rb0] + red_ss[3][rb0];
            float S1  = red_s [0][rb1] + red_s [1][rb1] + red_s [2][rb1] + red_s [3][rb1];
            float SS1 = red_ss[0][rb1] + red_ss[1][rb1] + red_ss[2][rb1] + red_ss[3][rb1];
            float mu0 = S0 * (1.f/128.f);
            float mu1 = S1 * (1.f/128.f);
            float rs0 = rsqrtf(SS0 * (1.f/128.f) - mu0*mu0 + EPSLN);
            float rs1 = rsqrtf(SS1 * (1.f/128.f) - mu1*mu1 + EPSLN);
            size_t r0 = (size_t)(m0 + rb0);
            size_t r1 = (size_t)(m0 + rb1);
#pragma unroll
            for (int ni = 0; ni < 4; ni++) {
                int c = wn + ni*8 + 2*t;
                float o0 = (acc[mi][ni][0] - mu0) * rs0 * ls2[ni].x + lb2[ni].x;
                float o1 = (acc[mi][ni][1] - mu0) * rs0 * ls2[ni].y + lb2[ni].y;
                float o2 = (acc[mi][ni][2] - mu1) * rs1 * ls2[ni].x + lb2[ni].x;
                float o3 = (acc[mi][ni][3] - mu1) * rs1 * ls2[ni].y + lb2[ni].y;
                *(float2*)&C[r0 * ldc + c] = make_float2(o0, o1);
                *(float2*)&C[r1 * ldc + c] = make_float2(o2, o3);
            }
        }
    }
}

// ============================================================================
// Elementwise gated-decay scan. 2048 independent (b,d) lanes, T steps each.
// ============================================================================
__global__ void scan_kernel(const float* __restrict__ Wpre,
                            const unsigned char* __restrict__ mask,
                            const float* __restrict__ mem0,
                            const float* __restrict__ decay_logit,
                            float* __restrict__ Mem,
                            float* __restrict__ out_final)
{
    int i = blockIdx.x * blockDim.x + threadIdx.x;   // 0..2047
    if (i >= BATCH * DB) return;
    int b = i >> 7;
    float dec = 1.f / (1.f + expf(-decay_logit[i & 127]));
    float omd = 1.f - dec;
    float m   = mem0[i];
#pragma unroll 4
    for (int t = 0; t < T_STEPS; t++) {
        Mem[(size_t)t * 2048 + i] = m;
        float w  = Wpre[(size_t)t * 2048 + i];
        float nm = dec * m + omd * w;
        m = mask[t * BATCH + b] ? m : nm;
    }
    out_final[i] = m;
}

// ============================================================================
// Final output LayerNorm over d_model=1024: out = LN(x + U) * s + b.
// One warp per row, 8 rows per block. Memory-bound.
// ============================================================================
__global__ void __launch_bounds__(256)
ln_out_kernel(const float* __restrict__ U,   // g_up = h2@Wu + bu
              const float* __restrict__ x,
              const float* __restrict__ lns,
              const float* __restrict__ lnb,
              float* __restrict__ out)
{
    const int lane = threadIdx.x & 31;
    const int w    = threadIdx.x >> 5;
    const size_t r = (size_t)blockIdx.x * 8 + w;

    const float4* x4 = (const float4*)(x + r * 1024);
    const float4* u4 = (const float4*)(U + r * 1024);

    float4 v[8];
    float s = 0.f, ss = 0.f;
#pragma unroll
    for (int c = 0; c < 8; c++) {
        int n4 = c * 32 + lane;
        float4 a = x4[n4];
        float4 b = u4[n4];
        float4 t;
        t.x = a.x + b.x; t.y = a.y + b.y; t.z = a.z + b.z; t.w = a.w + b.w;
        v[c] = t;
        s  += t.x + t.y + t.z + t.w;
        ss += t.x*t.x + t.y*t.y + t.z*t.z + t.w*t.w;
    }
#pragma unroll
    for (int o = 16; o > 0; o >>= 1) {
        s  += __shfl_xor_sync(0xffffffffu, s,  o);
        ss += __shfl_xor_sync(0xffffffffu, ss, o);
    }
    float mu = s * (1.f/1024.f);
    float rs = rsqrtf(ss * (1.f/1024.f) - mu*mu + EPSLN);

    float4* o4 = (float4*)(out + r * 1024);
#pragma unroll
    for (int c = 0; c < 8; c++) {
        int n4 = c * 32 + lane;
        float4 s4 = *(const float4*)&lns[n4 * 4];
        float4 b4 = *(const float4*)&lnb[n4 * 4];
        float4 t = v[c];
        float4 o;
        o.x = (t.x - mu) * rs * s4.x + b4.x;
        o.y = (t.y - mu) * rs * s4.y + b4.y;
        o.z = (t.z - mu) * rs * s4.z + b4.z;
        o.w = (t.w - mu) * rs * s4.w + b4.w;
        o4[n4] = o;
    }
}

// ============================================================================
extern "C" void kernel_launch(void* const* d_in, const int* in_sizes, int n_in,
                              void* d_out, int out_size)
{
    const float*         x     = (const float*)d_in[0];
    const unsigned char* mask  = (const unsigned char*)d_in[1];
    const float*         mem0  = (const float*)d_in[2];
    const float*         Wb    = (const float*)d_in[3];
    const float*         bb    = (const float*)d_in[4];
    const float*         Wu    = (const float*)d_in[5];
    const float*         bu    = (const float*)d_in[6];
    const float*         Wr    = (const float*)d_in[7];
    const float*         br    = (const float*)d_in[8];
    const float*         Ww    = (const float*)d_in[9];
    const float*         bw    = (const float*)d_in[10];
    const float*         dlg   = (const float*)d_in[11];
    const float*         ffw1  = (const float*)d_in[12];
    const float*         ffb1  = (const float*)d_in[13];
    const float*         ffw2  = (const float*)d_in[14];
    const float*         ffb2  = (const float*)d_in[15];
    const float*         mlns  = (const float*)d_in[16];
    const float*         mlnb  = (const float*)d_in[17];
    const float*         flns  = (const float*)d_in[18];
    const float*         flnb  = (const float*)d_in[19];
    const float*         olns  = (const float*)d_in[20];
    const float*         olnb  = (const float*)d_in[21];
    float* out = (float*)d_out;

    float *H, *Wpre, *Mem, *h1, *hid, *h2, *up;
    cudaGetSymbolAddress((void**)&H,    g_H);
    cudaGetSymbolAddress((void**)&Wpre, g_Wpre);
    cudaGetSymbolAddress((void**)&Mem,  g_Mem);
    cudaGetSymbolAddress((void**)&h1,   g_h1);
    cudaGetSymbolAddress((void**)&hid,  g_hid);
    cudaGetSymbolAddress((void**)&h2,   g_h2);
    cudaGetSymbolAddress((void**)&up,   g_up);

    dim3 blk(256);

    // 1) H = x @ Wb + bb                    (K=1024, N=128)
    mma_gemm<1024,0><<<dim3(1,256), blk>>>(x, 1024, Wb, 128, bb,
                                           nullptr, nullptr, nullptr, H, 128);
    // 2) Wpre = tanh(H @ Ww + bw)           (K=128, N=128)
    mma_gemm<128,1><<<dim3(1,256), blk>>>(H, 128, Ww, 128, bw,
                                          nullptr, nullptr, nullptr, Wpre, 128);
    // 3) elementwise gated-decay scan -> Mem[t], final mem -> out tail
    scan_kernel<<<8, 256>>>(Wpre, mask, mem0, dlg, Mem,
                            out + (size_t)ROWS * DM);
    // 4) h1 = LN(H + Mem@Wr + br) * mln_s + mln_b     (K=128, N=128)
    mma_gemm<128,3><<<dim3(1,256), blk>>>(Mem, 128, Wr, 128, br,
                                          H, mlns, mlnb, h1, 128);
    // 5) hid = relu(h1 @ ff_w1 + ff_b1)     (K=128, N=512)
    mma_gemm<128,2><<<dim3(4,256), blk>>>(h1, 128, ffw1, 512, ffb1,
                                          nullptr, nullptr, nullptr, hid, 512);
    // 6) h2 = LN(h1 + hid@ff_w2 + ff_b2) * fln_s + fln_b   (K=512, N=128)
    mma_gemm<512,3><<<dim3(1,256), blk>>>(hid, 512, ffw2, 128, ffb2,
                                          h1, flns, flnb, h2, 128);
    // 7) up = h2 @ Wu + bu                  (K=128, N=1024)
    mma_gemm<128,0><<<dim3(8,256), blk>>>(h2, 128, Wu, 1024, bu,
                                          nullptr, nullptr, nullptr, up, 1024);
    // 8) out = LN(x + up) * oln_s + oln_b
    ln_out_kernel<<<ROWS/8, blk>>>(up, x, olns, olnb, out);

    (void)in_sizes; (void)n_in; (void)out_size;
}

// round 11
// speedup vs baseline: 3.2230x; 2.0553x over previous
#include <cuda_runtime.h>
#include <math.h>
#include <stdint.h>

#define T_STEPS 2048
#define BATCH   16
#define DM      1024
#define DB      128
#define DH      512
#define ROWS    (T_STEPS*BATCH)   /* 32768 */
#define EPSLN   1e-5f
#define CH      32                /* scan chunk length */
#define NCH     (T_STEPS/CH)      /* 64 chunks */

// ---------------- scratch (no allocations allowed; static device globals) ---
__device__ float g_H[ROWS*DB];
__device__ float g_Wpre[ROWS*DB];
__device__ float g_Mem[ROWS*DB];
__device__ float g_h1[ROWS*DB];
__device__ float g_hid[ROWS*DH];
__device__ float g_h2[ROWS*DB];
__device__ float g_up[ROWS*DM];
__device__ float g_cA[NCH*2048];  // per-chunk affine composite A
__device__ float g_cB[NCH*2048];  // per-chunk affine composite B
__device__ float g_cM[NCH*2048];  // chunk-initial mem state

// ---------------------------------------------------------------------------
__device__ __forceinline__ uint32_t f2tf32(float f) {
    uint32_t r;
    asm("cvt.rna.tf32.f32 %0, %1;" : "=r"(r) : "f"(f));
    return r;
}
__device__ __forceinline__ void mma8(float& d0, float& d1, float& d2, float& d3,
                                     uint32_t a0, uint32_t a1, uint32_t a2, uint32_t a3,
                                     uint32_t b0, uint32_t b1)
{
    asm volatile(
        "mma.sync.aligned.m16n8k8.row.col.f32.tf32.tf32.f32 "
        "{%0,%1,%2,%3}, {%4,%5,%6,%7}, {%8,%9}, {%0,%1,%2,%3};"
        : "+f"(d0), "+f"(d1), "+f"(d2), "+f"(d3)
        : "r"(a0), "r"(a1), "r"(a2), "r"(a3), "r"(b0), "r"(b1));
}
__device__ __forceinline__ void cp_async16(void* smem_dst, const void* gsrc) {
    uint32_t d = (uint32_t)__cvta_generic_to_shared(smem_dst);
    asm volatile("cp.async.cg.shared.global [%0], [%1], 16;\n" :: "r"(d), "l"(gsrc));
}
__device__ __forceinline__ void cp_commit() {
    asm volatile("cp.async.commit_group;\n" ::: "memory");
}
template<int N> __device__ __forceinline__ void cp_wait() {
    asm volatile("cp.async.wait_group %0;\n" :: "n"(N) : "memory");
}

// SMEM layout (floats):
//   As: 2 bufs x 128 rows x 36 (32 K + 4 pad)   -> bank(4m+k), conflict-free frags
//   Bs: 2 bufs x 32  rows x 136 (128 N + 8 pad) -> bank(8k+n), conflict-free frags
#define AS_STRIDE 36
#define BS_STRIDE 136
#define AS_BUF (128*AS_STRIDE)
#define BS_BUF (32*BS_STRIDE)
#define SMEM_FLOATS (2*AS_BUF + 2*BS_BUF + 2*512)
#define SMEM_BYTES  (SMEM_FLOATS*4)

// ============================================================================
// tf32 tensor-core GEMM, cp.async double-buffered. Block 128x128x32,
// 8 warps (2m x 4n), warp tile 64x32, mma m16n8k8.
// EPI: 0 = +bias, 1 = +bias,tanh, 2 = +bias,relu,
//      3 = +bias,+res, then LayerNorm over the 128-wide row (needs n0==0)
// ============================================================================
template<int KTOT, int EPI>
__global__ void __launch_bounds__(256, 2)
mma_gemm(const float* __restrict__ A, int lda,
         const float* __restrict__ Bw, int ldb,
         const float* __restrict__ bias,
         const float* __restrict__ res,
         const float* __restrict__ ln_s, const float* __restrict__ ln_b,
         float* __restrict__ C, int ldc)
{
    extern __shared__ float dynsm[];
    float* Asm   = dynsm;                       // [2][128][36]
    float* Bsm   = dynsm + 2*AS_BUF;            // [2][32][136]
    float* red_s  = Bsm + 2*BS_BUF;             // [4][128]
    float* red_ss = red_s + 512;                // [4][128]

    const int tid  = threadIdx.x;
    const int lane = tid & 31;
    const int wid  = tid >> 5;
    const int g    = lane >> 2;         // 0..7
    const int t    = lane & 3;          // 0..3
    const int wm   = (wid >> 2) * 64;
    const int wcol = wid & 3;
    const int wn   = wcol * 32;
    const int m0   = blockIdx.y * 128;
    const int n0   = blockIdx.x * 128;

    constexpr int NT = KTOT / 32;

    float acc[4][4][4];
#pragma unroll
    for (int mi = 0; mi < 4; mi++)
#pragma unroll
        for (int ni = 0; ni < 4; ni++)
#pragma unroll
            for (int r = 0; r < 4; r++) acc[mi][ni][r] = 0.f;

    // per-thread staging coords
    const int a_m  = tid >> 3;          // reused with +32 rows per it? no: idx pattern below
    const int a_kv = tid & 7;
    const int b_k  = tid >> 5;
    const int b_nv = tid & 31;

    auto load_tile = [&](int kt, int buf) {
        const int k0 = kt * 32;
        float* Ab = Asm + buf * AS_BUF;
        float* Bb = Bsm + buf * BS_BUF;
#pragma unroll
        for (int it = 0; it < 4; ++it) {
            int m = a_m + it * 32;
            cp_async16(&Ab[m * AS_STRIDE + a_kv * 4],
                       &A[(size_t)(m0 + m) * lda + k0 + a_kv * 4]);
        }
#pragma unroll
        for (int it = 0; it < 4; ++it) {
            int k = b_k + it * 8;
            cp_async16(&Bb[k * BS_STRIDE + b_nv * 4],
                       &Bw[(size_t)(k0 + k) * ldb + n0 + b_nv * 4]);
        }
    };

    load_tile(0, 0);
    cp_commit();

    for (int kt = 0; kt < NT; ++kt) {
        if (kt + 1 < NT) {
            load_tile(kt + 1, (kt + 1) & 1);
            cp_commit();
            cp_wait<1>();
        } else {
            cp_wait<0>();
        }
        __syncthreads();

        const float* Ab = Asm + (kt & 1) * AS_BUF;
        const float* Bb = Bsm + (kt & 1) * BS_BUF;
#pragma unroll
        for (int kk = 0; kk < 4; kk++) {
            uint32_t av[4][4];
#pragma unroll
            for (int mi = 0; mi < 4; mi++) {
                int r0 = wm + mi * 16 + g;
                av[mi][0] = f2tf32(Ab[ r0      * AS_STRIDE + kk*8 + t    ]);
                av[mi][1] = f2tf32(Ab[(r0 + 8) * AS_STRIDE + kk*8 + t    ]);
                av[mi][2] = f2tf32(Ab[ r0      * AS_STRIDE + kk*8 + t + 4]);
                av[mi][3] = f2tf32(Ab[(r0 + 8) * AS_STRIDE + kk*8 + t + 4]);
            }
            uint32_t bv[4][2];
#pragma unroll
            for (int ni = 0; ni < 4; ni++) {
                bv[ni][0] = f2tf32(Bb[(kk*8 + t    ) * BS_STRIDE + wn + ni*8 + g]);
                bv[ni][1] = f2tf32(Bb[(kk*8 + t + 4) * BS_STRIDE + wn + ni*8 + g]);
            }
#pragma unroll
            for (int mi = 0; mi < 4; mi++)
#pragma unroll
                for (int ni = 0; ni < 4; ni++)
                    mma8(acc[mi][ni][0], acc[mi][ni][1], acc[mi][ni][2], acc[mi][ni][3],
                         av[mi][0], av[mi][1], av[mi][2], av[mi][3],
                         bv[ni][0], bv[ni][1]);
        }
        __syncthreads();
    }

    // ---- epilogue ----------------------------------------------------------
    float2 bias2[4];
#pragma unroll
    for (int ni = 0; ni < 4; ni++)
        bias2[ni] = *(const float2*)&bias[n0 + wn + ni*8 + 2*t];

    if (EPI != 3) {
#pragma unroll
        for (int mi = 0; mi < 4; mi++) {
            size_t r0 = (size_t)(m0 + wm + mi*16 + g);
            size_t r1 = r0 + 8;
#pragma unroll
            for (int ni = 0; ni < 4; ni++) {
                int c = n0 + wn + ni*8 + 2*t;
                float v0 = acc[mi][ni][0] + bias2[ni].x;
                float v1 = acc[mi][ni][1] + bias2[ni].y;
                float v2 = acc[mi][ni][2] + bias2[ni].x;
                float v3 = acc[mi][ni][3] + bias2[ni].y;
                if (EPI == 1) { v0 = tanhf(v0); v1 = tanhf(v1); v2 = tanhf(v2); v3 = tanhf(v3); }
                if (EPI == 2) {
                    v0 = fmaxf(v0, 0.f); v1 = fmaxf(v1, 0.f);
                    v2 = fmaxf(v2, 0.f); v3 = fmaxf(v3, 0.f);
                }
                *(float2*)&C[r0 * ldc + c] = make_float2(v0, v1);
                *(float2*)&C[r1 * ldc + c] = make_float2(v2, v3);
            }
        }
    } else {
#pragma unroll
        for (int mi = 0; mi < 4; mi++) {
            size_t r0 = (size_t)(m0 + wm + mi*16 + g);
            size_t r1 = r0 + 8;
#pragma unroll
            for (int ni = 0; ni < 4; ni++) {
                int c = wn + ni*8 + 2*t;
                float2 rv0 = *(const float2*)&res[r0 * 128 + c];
                float2 rv1 = *(const float2*)&res[r1 * 128 + c];
                acc[mi][ni][0] += bias2[ni].x + rv0.x;
                acc[mi][ni][1] += bias2[ni].y + rv0.y;
                acc[mi][ni][2] += bias2[ni].x + rv1.x;
                acc[mi][ni][3] += bias2[ni].y + rv1.y;
            }
        }
#pragma unroll
        for (int mi = 0; mi < 4; mi++) {
            float s0 = 0.f, ss0 = 0.f, s1 = 0.f, ss1 = 0.f;
#pragma unroll
            for (int ni = 0; ni < 4; ni++) {
                float a0 = acc[mi][ni][0], a1 = acc[mi][ni][1];
                float a2 = acc[mi][ni][2], a3 = acc[mi][ni][3];
                s0 += a0 + a1;  ss0 += a0*a0 + a1*a1;
                s1 += a2 + a3;  ss1 += a2*a2 + a3*a3;
            }
#pragma unroll
            for (int o = 1; o <= 2; o <<= 1) {
                s0  += __shfl_xor_sync(0xffffffffu, s0,  o);
                ss0 += __shfl_xor_sync(0xffffffffu, ss0, o);
                s1  += __shfl_xor_sync(0xffffffffu, s1,  o);
                ss1 += __shfl_xor_sync(0xffffffffu, ss1, o);
            }
            if (t == 0) {
                int rb0 = wm + mi*16 + g;
                red_s [wcol*128 + rb0]     = s0;  red_ss[wcol*128 + rb0]     = ss0;
                red_s [wcol*128 + rb0 + 8] = s1;  red_ss[wcol*128 + rb0 + 8] = ss1;
            }
        }
        __syncthreads();

        float2 ls2[4], lb2[4];
#pragma unroll
        for (int ni = 0; ni < 4; ni++) {
            ls2[ni] = *(const float2*)&ln_s[wn + ni*8 + 2*t];
            lb2[ni] = *(const float2*)&ln_b[wn + ni*8 + 2*t];
        }
#pragma unroll
        for (int mi = 0; mi < 4; mi++) {
            int rb0 = wm + mi*16 + g;
            int rb1 = rb0 + 8;
            float S0  = red_s [rb0] + red_s [128+rb0] + red_s [256+rb0] + red_s [384+rb0];
            float SS0 = red_ss[rb0] + red_ss[128+rb0] + red_ss[256+rb0] + red_ss[384+rb0];
            float S1  = red_s [rb1] + red_s [128+rb1] + red_s [256+rb1] + red_s [384+rb1];
            float SS1 = red_ss[rb1] + red_ss[128+rb1] + red_ss[256+rb1] + red_ss[384+rb1];
            float mu0 = S0 * (1.f/128.f);
            float mu1 = S1 * (1.f/128.f);
            float rs0 = rsqrtf(SS0 * (1.f/128.f) - mu0*mu0 + EPSLN);
            float rs1 = rsqrtf(SS1 * (1.f/128.f) - mu1*mu1 + EPSLN);
            size_t r0 = (size_t)(m0 + rb0);
            size_t r1 = (size_t)(m0 + rb1);
#pragma unroll
            for (int ni = 0; ni < 4; ni++) {
                int c = wn + ni*8 + 2*t;
                float o0 = (acc[mi][ni][0] - mu0) * rs0 * ls2[ni].x + lb2[ni].x;
                float o1 = (acc[mi][ni][1] - mu0) * rs0 * ls2[ni].y + lb2[ni].y;
                float o2 = (acc[mi][ni][2] - mu1) * rs1 * ls2[ni].x + lb2[ni].x;
                float o3 = (acc[mi][ni][3] - mu1) * rs1 * ls2[ni].y + lb2[ni].y;
                *(float2*)&C[r0 * ldc + c] = make_float2(o0, o1);
                *(float2*)&C[r1 * ldc + c] = make_float2(o2, o3);
            }
        }
    }
}

// ============================================================================
// Chunked parallel scan of  m' = a*m + b,  a = mask?1:dec, b = mask?0:omd*w.
// Pass 1: per (lane, chunk) compose affine (A,B) over CH steps.
// Pass 2: per lane, scan NCH chunk summaries -> chunk-initial states + final.
// Pass 3: per (lane, chunk) replay, writing Mem[t].
// ============================================================================
__global__ void __launch_bounds__(256)
scan_pass1(const float* __restrict__ Wpre,
           const unsigned char* __restrict__ mask,
           const float* __restrict__ decay_logit,
           float* __restrict__ cA, float* __restrict__ cB)
{
    int idx = blockIdx.x * blockDim.x + threadIdx.x;   // 0 .. NCH*2048-1
    int i = idx & 2047;
    int c = idx >> 11;
    int b = i >> 7;
    float dec = 1.f / (1.f + expf(-decay_logit[i & 127]));
    float omd = 1.f - dec;
    float Aa = 1.f, Bb = 0.f;
#pragma unroll 4
    for (int s = 0; s < CH; s++) {
        int t = c * CH + s;
        bool mk = mask[t * BATCH + b];
        float w  = Wpre[(size_t)t * 2048 + i];
        float a  = mk ? 1.f : dec;
        float bt = mk ? 0.f : omd * w;
        Aa = a * Aa;
        Bb = a * Bb + bt;
    }
    cA[c * 2048 + i] = Aa;
    cB[c * 2048 + i] = Bb;
}

__global__ void __launch_bounds__(256)
scan_pass2(const float* __restrict__ cA, const float* __restrict__ cB,
           const float* __restrict__ mem0,
           float* __restrict__ cM, float* __restrict__ out_final)
{
    int i = blockIdx.x * blockDim.x + threadIdx.x;     // 0..2047
    if (i >= 2048) return;
    float m = mem0[i];
#pragma unroll 4
    for (int c = 0; c < NCH; c++) {
        cM[c * 2048 + i] = m;
        m = cA[c * 2048 + i] * m + cB[c * 2048 + i];
    }
    out_final[i] = m;
}

__global__ void __launch_bounds__(256)
scan_pass3(const float* __restrict__ Wpre,
           const unsigned char* __restrict__ mask,
           const float* __restrict__ decay_logit,
           const float* __restrict__ cM,
           float* __restrict__ Mem)
{
    int idx = blockIdx.x * blockDim.x + threadIdx.x;
    int i = idx & 2047;
    int c = idx >> 11;
    int b = i >> 7;
    float dec = 1.f / (1.f + expf(-decay_logit[i & 127]));
    float omd = 1.f - dec;
    float m = cM[c * 2048 + i];
#pragma unroll 4
    for (int s = 0; s < CH; s++) {
        int t = c * CH + s;
        Mem[(size_t)t * 2048 + i] = m;
        bool mk = mask[t * BATCH + b];
        float w  = Wpre[(size_t)t * 2048 + i];
        float nm = dec * m + omd * w;
        m = mk ? m : nm;
    }
}

// ============================================================================
// Final output LayerNorm over d_model=1024: out = LN(x + U) * s + b.
// ============================================================================
__global__ void __launch_bounds__(256)
ln_out_kernel(const float* __restrict__ U,
              const float* __restrict__ x,
              const float* __restrict__ lns,
              const float* __restrict__ lnb,
              float* __restrict__ out)
{
    const int lane = threadIdx.x & 31;
    const int w    = threadIdx.x >> 5;
    const size_t r = (size_t)blockIdx.x * 8 + w;

    const float4* x4 = (const float4*)(x + r * 1024);
    const float4* u4 = (const float4*)(U + r * 1024);

    float4 v[8];
    float s = 0.f, ss = 0.f;
#pragma unroll
    for (int c = 0; c < 8; c++) {
        int n4 = c * 32 + lane;
        float4 a = x4[n4];
        float4 b = u4[n4];
        float4 t;
        t.x = a.x + b.x; t.y = a.y + b.y; t.z = a.z + b.z; t.w = a.w + b.w;
        v[c] = t;
        s  += t.x + t.y + t.z + t.w;
        ss += t.x*t.x + t.y*t.y + t.z*t.z + t.w*t.w;
    }
#pragma unroll
    for (int o = 16; o > 0; o >>= 1) {
        s  += __shfl_xor_sync(0xffffffffu, s,  o);
        ss += __shfl_xor_sync(0xffffffffu, ss, o);
    }
    float mu = s * (1.f/1024.f);
    float rs = rsqrtf(ss * (1.f/1024.f) - mu*mu + EPSLN);

    float4* o4 = (float4*)(out + r * 1024);
#pragma unroll
    for (int c = 0; c < 8; c++) {
        int n4 = c * 32 + lane;
        float4 s4 = *(const float4*)&lns[n4 * 4];
        float4 b4 = *(const float4*)&lnb[n4 * 4];
        float4 t = v[c];
        float4 o;
        o.x = (t.x - mu) * rs * s4.x + b4.x;
        o.y = (t.y - mu) * rs * s4.y + b4.y;
        o.z = (t.z - mu) * rs * s4.z + b4.z;
        o.w = (t.w - mu) * rs * s4.w + b4.w;
        o4[n4] = o;
    }
}

// ============================================================================
extern "C" void kernel_launch(void* const* d_in, const int* in_sizes, int n_in,
                              void* d_out, int out_size)
{
    const float*         x     = (const float*)d_in[0];
    const unsigned char* mask  = (const unsigned char*)d_in[1];
    const float*         mem0  = (const float*)d_in[2];
    const float*         Wb    = (const float*)d_in[3];
    const float*         bb    = (const float*)d_in[4];
    const float*         Wu    = (const float*)d_in[5];
    const float*         bu    = (const float*)d_in[6];
    const float*         Wr    = (const float*)d_in[7];
    const float*         br    = (const float*)d_in[8];
    const float*         Ww    = (const float*)d_in[9];
    const float*         bw    = (const float*)d_in[10];
    const float*         dlg   = (const float*)d_in[11];
    const float*         ffw1  = (const float*)d_in[12];
    const float*         ffb1  = (const float*)d_in[13];
    const float*         ffw2  = (const float*)d_in[14];
    const float*         ffb2  = (const float*)d_in[15];
    const float*         mlns  = (const float*)d_in[16];
    const float*         mlnb  = (const float*)d_in[17];
    const float*         flns  = (const float*)d_in[18];
    const float*         flnb  = (const float*)d_in[19];
    const float*         olns  = (const float*)d_in[20];
    const float*         olnb  = (const float*)d_in[21];
    float* out = (float*)d_out;

    float *H, *Wpre, *Mem, *h1, *hid, *h2, *up, *cA, *cB, *cM;
    cudaGetSymbolAddress((void**)&H,    g_H);
    cudaGetSymbolAddress((void**)&Wpre, g_Wpre);
    cudaGetSymbolAddress((void**)&Mem,  g_Mem);
    cudaGetSymbolAddress((void**)&h1,   g_h1);
    cudaGetSymbolAddress((void**)&hid,  g_hid);
    cudaGetSymbolAddress((void**)&h2,   g_h2);
    cudaGetSymbolAddress((void**)&up,   g_up);
    cudaGetSymbolAddress((void**)&cA,   g_cA);
    cudaGetSymbolAddress((void**)&cB,   g_cB);
    cudaGetSymbolAddress((void**)&cM,   g_cM);

    static bool attr_done = false;
    if (!attr_done) {
        cudaFuncSetAttribute(mma_gemm<1024,0>, cudaFuncAttributeMaxDynamicSharedMemorySize, SMEM_BYTES);
        cudaFuncSetAttribute(mma_gemm< 128,0>, cudaFuncAttributeMaxDynamicSharedMemorySize, SMEM_BYTES);
        cudaFuncSetAttribute(mma_gemm< 128,1>, cudaFuncAttributeMaxDynamicSharedMemorySize, SMEM_BYTES);
        cudaFuncSetAttribute(mma_gemm< 128,2>, cudaFuncAttributeMaxDynamicSharedMemorySize, SMEM_BYTES);
        cudaFuncSetAttribute(mma_gemm< 128,3>, cudaFuncAttributeMaxDynamicSharedMemorySize, SMEM_BYTES);
        cudaFuncSetAttribute(mma_gemm< 512,3>, cudaFuncAttributeMaxDynamicSharedMemorySize, SMEM_BYTES);
        attr_done = true;
    }

    dim3 blk(256);

    // 1) H = x @ Wb + bb                    (K=1024, N=128)
    mma_gemm<1024,0><<<dim3(1,256), blk, SMEM_BYTES>>>(x, 1024, Wb, 128, bb,
                                           nullptr, nullptr, nullptr, H, 128);
    // 2) Wpre = tanh(H @ Ww + bw)           (K=128, N=128)
    mma_gemm<128,1><<<dim3(1,256), blk, SMEM_BYTES>>>(H, 128, Ww, 128, bw,
                                          nullptr, nullptr, nullptr, Wpre, 128);
    // 3) chunked parallel scan -> Mem[t], final mem -> out tail
    scan_pass1<<<NCH*2048/256, blk>>>(Wpre, mask, dlg, cA, cB);
    scan_pass2<<<8, blk>>>(cA, cB, mem0, cM, out + (size_t)ROWS * DM);
    scan_pass3<<<NCH*2048/256, blk>>>(Wpre, mask, dlg, cM, Mem);
    // 4) h1 = LN(H + Mem@Wr + br) * mln_s + mln_b     (K=128, N=128)
    mma_gemm<128,3><<<dim3(1,256), blk, SMEM_BYTES>>>(Mem, 128, Wr, 128, br,
                                          H, mlns, mlnb, h1, 128);
    // 5) hid = relu(h1 @ ff_w1 + ff_b1)     (K=128, N=512)
    mma_gemm<128,2><<<dim3(4,256), blk, SMEM_BYTES>>>(h1, 128, ffw1, 512, ffb1,
                                          nullptr, nullptr, nullptr, hid, 512);
    // 6) h2 = LN(h1 + hid@ff_w2 + ff_b2) * fln_s + fln_b   (K=512, N=128)
    mma_gemm<512,3><<<dim3(1,256), blk, SMEM_BYTES>>>(hid, 512, ffw2, 128, ffb2,
                                          h1, flns, flnb, h2, 128);
    // 7) up = h2 @ Wu + bu                  (K=128, N=1024)
    mma_gemm<128,0><<<dim3(8,256), blk, SMEM_BYTES>>>(h2, 128, Wu, 1024, bu,
                                          nullptr, nullptr, nullptr, up, 1024);
    // 8) out = LN(x + up) * oln_s + oln_b
    ln_out_kernel<<<ROWS/8, blk>>>(up, x, olns, olnb, out);

    (void)in_sizes; (void)n_in; (void)out_size;
}

// round 12
// speedup vs baseline: 3.2582x; 1.0109x over previous
#include <cuda_runtime.h>
#include <math.h>
#include <stdint.h>

#define T_STEPS 2048
#define BATCH   16
#define DM      1024
#define DB      128
#define DH      512
#define ROWS    (T_STEPS*BATCH)   /* 32768 */
#define EPSLN   1e-5f
#define CH      64                /* scan chunk length */
#define NCH     (T_STEPS/CH)      /* 32 chunks -> one warp per lane */

// ---------------- scratch (no allocations allowed; static device globals) ---
__device__ float g_H[ROWS*DB];
__device__ float g_Wpre[ROWS*DB];
__device__ float g_Mem[ROWS*DB];
__device__ float g_h1[ROWS*DB];
__device__ float g_hid[ROWS*DH];
__device__ float g_h2[ROWS*DB];
__device__ float g_cA[NCH*2048];  // per-chunk affine composite A
__device__ float g_cB[NCH*2048];  // per-chunk affine composite B
__device__ float g_cM[NCH*2048];  // chunk-initial mem state
__device__ float g_ps [ROWS*8];   // per-(row, n-block) partial sum   (GEMM7)
__device__ float g_pss[ROWS*8];   // per-(row, n-block) partial sumsq (GEMM7)

// ---------------------------------------------------------------------------
__device__ __forceinline__ uint32_t f2tf32(float f) {
    uint32_t r;
    asm("cvt.rna.tf32.f32 %0, %1;" : "=r"(r) : "f"(f));
    return r;
}
__device__ __forceinline__ void mma8(float& d0, float& d1, float& d2, float& d3,
                                     uint32_t a0, uint32_t a1, uint32_t a2, uint32_t a3,
                                     uint32_t b0, uint32_t b1)
{
    asm volatile(
        "mma.sync.aligned.m16n8k8.row.col.f32.tf32.tf32.f32 "
        "{%0,%1,%2,%3}, {%4,%5,%6,%7}, {%8,%9}, {%0,%1,%2,%3};"
        : "+f"(d0), "+f"(d1), "+f"(d2), "+f"(d3)
        : "r"(a0), "r"(a1), "r"(a2), "r"(a3), "r"(b0), "r"(b1));
}
__device__ __forceinline__ void cp_async16(void* smem_dst, const void* gsrc) {
    uint32_t d = (uint32_t)__cvta_generic_to_shared(smem_dst);
    asm volatile("cp.async.cg.shared.global [%0], [%1], 16;\n" :: "r"(d), "l"(gsrc));
}
__device__ __forceinline__ void cp_commit() {
    asm volatile("cp.async.commit_group;\n" ::: "memory");
}
template<int N> __device__ __forceinline__ void cp_wait() {
    asm volatile("cp.async.wait_group %0;\n" :: "n"(N) : "memory");
}

#define AS_STRIDE 36
#define BS_STRIDE 136
#define AS_BUF (128*AS_STRIDE)
#define BS_BUF (32*BS_STRIDE)
#define SMEM_FLOATS (2*AS_BUF + 2*BS_BUF + 2*512)
#define SMEM_BYTES  (SMEM_FLOATS*4)

// ============================================================================
// tf32 tensor-core GEMM, cp.async double-buffered. Block 128x128x32,
// 8 warps (2m x 4n), warp tile 64x32, mma m16n8k8.
// EPI: 0 = +bias, 1 = +bias,tanh, 2 = +bias,relu,
//      3 = +bias,+res(ldc-stride), LayerNorm over 128-wide row (needs n0==0)
//      4 = +bias,+res(ldc-stride at global col), write v, emit partial s/ss
// ============================================================================
template<int KTOT, int EPI>
__global__ void __launch_bounds__(256, 2)
mma_gemm(const float* __restrict__ A, int lda,
         const float* __restrict__ Bw, int ldb,
         const float* __restrict__ bias,
         const float* __restrict__ res,
         const float* __restrict__ ln_s, const float* __restrict__ ln_b,
         float* __restrict__ C, int ldc,
         float* __restrict__ ps, float* __restrict__ pss)
{
    extern __shared__ float dynsm[];
    float* Asm   = dynsm;                       // [2][128][36]
    float* Bsm   = dynsm + 2*AS_BUF;            // [2][32][136]
    float* red_s  = Bsm + 2*BS_BUF;             // [4][128]
    float* red_ss = red_s + 512;                // [4][128]

    const int tid  = threadIdx.x;
    const int lane = tid & 31;
    const int wid  = tid >> 5;
    const int g    = lane >> 2;         // 0..7
    const int t    = lane & 3;          // 0..3
    const int wm   = (wid >> 2) * 64;
    const int wcol = wid & 3;
    const int wn   = wcol * 32;
    const int m0   = blockIdx.y * 128;
    const int n0   = blockIdx.x * 128;

    constexpr int NT = KTOT / 32;

    float acc[4][4][4];
#pragma unroll
    for (int mi = 0; mi < 4; mi++)
#pragma unroll
        for (int ni = 0; ni < 4; ni++)
#pragma unroll
            for (int r = 0; r < 4; r++) acc[mi][ni][r] = 0.f;

    const int a_m  = tid >> 3;
    const int a_kv = tid & 7;
    const int b_k  = tid >> 5;
    const int b_nv = tid & 31;

    auto load_tile = [&](int kt, int buf) {
        const int k0 = kt * 32;
        float* Ab = Asm + buf * AS_BUF;
        float* Bb = Bsm + buf * BS_BUF;
#pragma unroll
        for (int it = 0; it < 4; ++it) {
            int m = a_m + it * 32;
            cp_async16(&Ab[m * AS_STRIDE + a_kv * 4],
                       &A[(size_t)(m0 + m) * lda + k0 + a_kv * 4]);
        }
#pragma unroll
        for (int it = 0; it < 4; ++it) {
            int k = b_k + it * 8;
            cp_async16(&Bb[k * BS_STRIDE + b_nv * 4],
                       &Bw[(size_t)(k0 + k) * ldb + n0 + b_nv * 4]);
        }
    };

    load_tile(0, 0);
    cp_commit();

    for (int kt = 0; kt < NT; ++kt) {
        if (kt + 1 < NT) {
            load_tile(kt + 1, (kt + 1) & 1);
            cp_commit();
            cp_wait<1>();
        } else {
            cp_wait<0>();
        }
        __syncthreads();

        const float* Ab = Asm + (kt & 1) * AS_BUF;
        const float* Bb = Bsm + (kt & 1) * BS_BUF;
#pragma unroll
        for (int kk = 0; kk < 4; kk++) {
            uint32_t av[4][4];
#pragma unroll
            for (int mi = 0; mi < 4; mi++) {
                int r0 = wm + mi * 16 + g;
                av[mi][0] = f2tf32(Ab[ r0      * AS_STRIDE + kk*8 + t    ]);
                av[mi][1] = f2tf32(Ab[(r0 + 8) * AS_STRIDE + kk*8 + t    ]);
                av[mi][2] = f2tf32(Ab[ r0      * AS_STRIDE + kk*8 + t + 4]);
                av[mi][3] = f2tf32(Ab[(r0 + 8) * AS_STRIDE + kk*8 + t + 4]);
            }
            uint32_t bv[4][2];
#pragma unroll
            for (int ni = 0; ni < 4; ni++) {
                bv[ni][0] = f2tf32(Bb[(kk*8 + t    ) * BS_STRIDE + wn + ni*8 + g]);
                bv[ni][1] = f2tf32(Bb[(kk*8 + t + 4) * BS_STRIDE + wn + ni*8 + g]);
            }
#pragma unroll
            for (int mi = 0; mi < 4; mi++)
#pragma unroll
                for (int ni = 0; ni < 4; ni++)
                    mma8(acc[mi][ni][0], acc[mi][ni][1], acc[mi][ni][2], acc[mi][ni][3],
                         av[mi][0], av[mi][1], av[mi][2], av[mi][3],
                         bv[ni][0], bv[ni][1]);
        }
        __syncthreads();
    }

    // ---- epilogue ----------------------------------------------------------
    float2 bias2[4];
#pragma unroll
    for (int ni = 0; ni < 4; ni++)
        bias2[ni] = *(const float2*)&bias[n0 + wn + ni*8 + 2*t];

    if (EPI == 0 || EPI == 1 || EPI == 2) {
#pragma unroll
        for (int mi = 0; mi < 4; mi++) {
            size_t r0 = (size_t)(m0 + wm + mi*16 + g);
            size_t r1 = r0 + 8;
#pragma unroll
            for (int ni = 0; ni < 4; ni++) {
                int c = n0 + wn + ni*8 + 2*t;
                float v0 = acc[mi][ni][0] + bias2[ni].x;
                float v1 = acc[mi][ni][1] + bias2[ni].y;
                float v2 = acc[mi][ni][2] + bias2[ni].x;
                float v3 = acc[mi][ni][3] + bias2[ni].y;
                if (EPI == 1) { v0 = tanhf(v0); v1 = tanhf(v1); v2 = tanhf(v2); v3 = tanhf(v3); }
                if (EPI == 2) {
                    v0 = fmaxf(v0, 0.f); v1 = fmaxf(v1, 0.f);
                    v2 = fmaxf(v2, 0.f); v3 = fmaxf(v3, 0.f);
                }
                *(float2*)&C[r0 * ldc + c] = make_float2(v0, v1);
                *(float2*)&C[r1 * ldc + c] = make_float2(v2, v3);
            }
        }
    } else if (EPI == 4) {
        // v = acc + bias + res (res strided by ldc, global column); store v;
        // emit per-(row, n-block) partial sum / sumsq for deferred LayerNorm.
#pragma unroll
        for (int mi = 0; mi < 4; mi++) {
            size_t r0 = (size_t)(m0 + wm + mi*16 + g);
            size_t r1 = r0 + 8;
#pragma unroll
            for (int ni = 0; ni < 4; ni++) {
                int c = n0 + wn + ni*8 + 2*t;
                float2 rv0 = *(const float2*)&res[r0 * ldc + c];
                float2 rv1 = *(const float2*)&res[r1 * ldc + c];
                acc[mi][ni][0] += bias2[ni].x + rv0.x;
                acc[mi][ni][1] += bias2[ni].y + rv0.y;
                acc[mi][ni][2] += bias2[ni].x + rv1.x;
                acc[mi][ni][3] += bias2[ni].y + rv1.y;
                *(float2*)&C[r0 * ldc + c] = make_float2(acc[mi][ni][0], acc[mi][ni][1]);
                *(float2*)&C[r1 * ldc + c] = make_float2(acc[mi][ni][2], acc[mi][ni][3]);
            }
        }
#pragma unroll
        for (int mi = 0; mi < 4; mi++) {
            float s0 = 0.f, ss0 = 0.f, s1 = 0.f, ss1 = 0.f;
#pragma unroll
            for (int ni = 0; ni < 4; ni++) {
                float a0 = acc[mi][ni][0], a1 = acc[mi][ni][1];
                float a2 = acc[mi][ni][2], a3 = acc[mi][ni][3];
                s0 += a0 + a1;  ss0 += a0*a0 + a1*a1;
                s1 += a2 + a3;  ss1 += a2*a2 + a3*a3;
            }
#pragma unroll
            for (int o = 1; o <= 2; o <<= 1) {
                s0  += __shfl_xor_sync(0xffffffffu, s0,  o);
                ss0 += __shfl_xor_sync(0xffffffffu, ss0, o);
                s1  += __shfl_xor_sync(0xffffffffu, s1,  o);
                ss1 += __shfl_xor_sync(0xffffffffu, ss1, o);
            }
            if (t == 0) {
                int rb0 = wm + mi*16 + g;
                red_s [wcol*128 + rb0]     = s0;  red_ss[wcol*128 + rb0]     = ss0;
                red_s [wcol*128 + rb0 + 8] = s1;  red_ss[wcol*128 + rb0 + 8] = ss1;
            }
        }
        __syncthreads();
        if (tid < 128) {
            float S  = red_s [tid] + red_s [128+tid] + red_s [256+tid] + red_s [384+tid];
            float SS = red_ss[tid] + red_ss[128+tid] + red_ss[256+tid] + red_ss[384+tid];
            size_t row = (size_t)(m0 + tid);
            ps [row * 8 + blockIdx.x] = S;
            pss[row * 8 + blockIdx.x] = SS;
        }
    } else {    // EPI == 3
#pragma unroll
        for (int mi = 0; mi < 4; mi++) {
            size_t r0 = (size_t)(m0 + wm + mi*16 + g);
            size_t r1 = r0 + 8;
#pragma unroll
            for (int ni = 0; ni < 4; ni++) {
                int c = wn + ni*8 + 2*t;
                float2 rv0 = *(const float2*)&res[r0 * 128 + c];
                float2 rv1 = *(const float2*)&res[r1 * 128 + c];
                acc[mi][ni][0] += bias2[ni].x + rv0.x;
                acc[mi][ni][1] += bias2[ni].y + rv0.y;
                acc[mi][ni][2] += bias2[ni].x + rv1.x;
                acc[mi][ni][3] += bias2[ni].y + rv1.y;
            }
        }
#pragma unroll
        for (int mi = 0; mi < 4; mi++) {
            float s0 = 0.f, ss0 = 0.f, s1 = 0.f, ss1 = 0.f;
#pragma unroll
            for (int ni = 0; ni < 4; ni++) {
                float a0 = acc[mi][ni][0], a1 = acc[mi][ni][1];
                float a2 = acc[mi][ni][2], a3 = acc[mi][ni][3];
                s0 += a0 + a1;  ss0 += a0*a0 + a1*a1;
                s1 += a2 + a3;  ss1 += a2*a2 + a3*a3;
            }
#pragma unroll
            for (int o = 1; o <= 2; o <<= 1) {
                s0  += __shfl_xor_sync(0xffffffffu, s0,  o);
                ss0 += __shfl_xor_sync(0xffffffffu, ss0, o);
                s1  += __shfl_xor_sync(0xffffffffu, s1,  o);
                ss1 += __shfl_xor_sync(0xffffffffu, ss1, o);
            }
            if (t == 0) {
                int rb0 = wm + mi*16 + g;
                red_s [wcol*128 + rb0]     = s0;  red_ss[wcol*128 + rb0]     = ss0;
                red_s [wcol*128 + rb0 + 8] = s1;  red_ss[wcol*128 + rb0 + 8] = ss1;
            }
        }
        __syncthreads();

        float2 ls2[4], lb2[4];
#pragma unroll
        for (int ni = 0; ni < 4; ni++) {
            ls2[ni] = *(const float2*)&ln_s[wn + ni*8 + 2*t];
            lb2[ni] = *(const float2*)&ln_b[wn + ni*8 + 2*t];
        }
#pragma unroll
        for (int mi = 0; mi < 4; mi++) {
            int rb0 = wm + mi*16 + g;
            int rb1 = rb0 + 8;
            float S0  = red_s [rb0] + red_s [128+rb0] + red_s [256+rb0] + red_s [384+rb0];
            float SS0 = red_ss[rb0] + red_ss[128+rb0] + red_ss[256+rb0] + red_ss[384+rb0];
            float S1  = red_s [rb1] + red_s [128+rb1] + red_s [256+rb1] + red_s [384+rb1];
            float SS1 = red_ss[rb1] + red_ss[128+rb1] + red_ss[256+rb1] + red_ss[384+rb1];
            float mu0 = S0 * (1.f/128.f);
            float mu1 = S1 * (1.f/128.f);
            float rs0 = rsqrtf(SS0 * (1.f/128.f) - mu0*mu0 + EPSLN);
            float rs1 = rsqrtf(SS1 * (1.f/128.f) - mu1*mu1 + EPSLN);
            size_t r0 = (size_t)(m0 + rb0);
            size_t r1 = (size_t)(m0 + rb1);
#pragma unroll
            for (int ni = 0; ni < 4; ni++) {
                int c = wn + ni*8 + 2*t;
                float o0 = (acc[mi][ni][0] - mu0) * rs0 * ls2[ni].x + lb2[ni].x;
                float o1 = (acc[mi][ni][1] - mu0) * rs0 * ls2[ni].y + lb2[ni].y;
                float o2 = (acc[mi][ni][2] - mu1) * rs1 * ls2[ni].x + lb2[ni].x;
                float o3 = (acc[mi][ni][3] - mu1) * rs1 * ls2[ni].y + lb2[ni].y;
                *(float2*)&C[r0 * ldc + c] = make_float2(o0, o1);
                *(float2*)&C[r1 * ldc + c] = make_float2(o2, o3);
            }
        }
    }
}

// ============================================================================
// Chunked parallel scan of  m' = a*m + b,  a = mask?1:dec, b = mask?0:omd*w.
// ============================================================================
__global__ void __launch_bounds__(256)
scan_pass1(const float* __restrict__ Wpre,
           const unsigned char* __restrict__ mask,
           const float* __restrict__ decay_logit,
           float* __restrict__ cA, float* __restrict__ cB)
{
    int idx = blockIdx.x * blockDim.x + threadIdx.x;   // 0 .. NCH*2048-1
    int i = idx & 2047;
    int c = idx >> 11;
    int b = i >> 7;
    float dec = 1.f / (1.f + expf(-decay_logit[i & 127]));
    float omd = 1.f - dec;
    float Aa = 1.f, Bb = 0.f;
#pragma unroll 4
    for (int s = 0; s < CH; s++) {
        int t = c * CH + s;
        bool mk = mask[t * BATCH + b];
        float w  = Wpre[(size_t)t * 2048 + i];
        float a  = mk ? 1.f : dec;
        float bt = mk ? 0.f : omd * w;
        Aa = a * Aa;
        Bb = a * Bb + bt;
    }
    cA[c * 2048 + i] = Aa;
    cB[c * 2048 + i] = Bb;
}

// Warp-shuffle affine scan over the NCH=32 chunk summaries of each lane.
// One warp per lane i; lane-of-warp = chunk index c.
__global__ void __launch_bounds__(256)
scan_pass2(const float* __restrict__ cA, const float* __restrict__ cB,
           const float* __restrict__ mem0,
           float* __restrict__ cM, float* __restrict__ out_final)
{
    int gt = blockIdx.x * blockDim.x + threadIdx.x;    // 0 .. 65535
    int i  = gt >> 5;                                  // lane 0..2047
    int c  = gt & 31;                                  // chunk 0..31
    float A = cA[c * 2048 + i];
    float B = cB[c * 2048 + i];
    // inclusive scan: (A,B) <- (A,B) ∘ prefix
#pragma unroll
    for (int o = 1; o < 32; o <<= 1) {
        float Ap = __shfl_up_sync(0xffffffffu, A, o);
        float Bp = __shfl_up_sync(0xffffffffu, B, o);
        if (c >= o) { B = A * Bp + B; A = A * Ap; }
    }
    float Ae = __shfl_up_sync(0xffffffffu, A, 1);
    float Be = __shfl_up_sync(0xffffffffu, B, 1);
    if (c == 0) { Ae = 1.f; Be = 0.f; }
    float m0v = mem0[i];
    cM[c * 2048 + i] = Ae * m0v + Be;                  // state entering chunk c
    if (c == 31) out_final[i] = A * m0v + B;           // final state
}

__global__ void __launch_bounds__(256)
scan_pass3(const float* __restrict__ Wpre,
           const unsigned char* __restrict__ mask,
           const float* __restrict__ decay_logit,
           const float* __restrict__ cM,
           float* __restrict__ Mem)
{
    int idx = blockIdx.x * blockDim.x + threadIdx.x;
    int i = idx & 2047;
    int c = idx >> 11;
    int b = i >> 7;
    float dec = 1.f / (1.f + expf(-decay_logit[i & 127]));
    float omd = 1.f - dec;
    float m = cM[c * 2048 + i];
#pragma unroll 4
    for (int s = 0; s < CH; s++) {
        int t = c * CH + s;
        Mem[(size_t)t * 2048 + i] = m;
        bool mk = mask[t * BATCH + b];
        float w  = Wpre[(size_t)t * 2048 + i];
        float nm = dec * m + omd * w;
        m = mk ? m : nm;
    }
}

// ============================================================================
// Deferred output LayerNorm: reduce the 8 per-block partials per row, then
// normalize out[] in place. One warp per row, 8 rows per block.
// ============================================================================
__global__ void __launch_bounds__(256)
norm_kernel(const float* __restrict__ ps, const float* __restrict__ pss,
            const float* __restrict__ lns, const float* __restrict__ lnb,
            float* __restrict__ out)
{
    const int lane = threadIdx.x & 31;
    const int w    = threadIdx.x >> 5;
    const size_t r = (size_t)blockIdx.x * 8 + w;

    float s  = (lane < 8) ? ps [r * 8 + lane] : 0.f;
    float ss = (lane < 8) ? pss[r * 8 + lane] : 0.f;
#pragma unroll
    for (int o = 4; o > 0; o >>= 1) {
        s  += __shfl_xor_sync(0xffffffffu, s,  o);
        ss += __shfl_xor_sync(0xffffffffu, ss, o);
    }
    s  = __shfl_sync(0xffffffffu, s,  0);
    ss = __shfl_sync(0xffffffffu, ss, 0);
    float mu = s * (1.f/1024.f);
    float rs = rsqrtf(ss * (1.f/1024.f) - mu*mu + EPSLN);

    float4* o4 = (float4*)(out + r * 1024);
#pragma unroll
    for (int c = 0; c < 8; c++) {
        int n4 = c * 32 + lane;
        float4 s4 = *(const float4*)&lns[n4 * 4];
        float4 b4 = *(const float4*)&lnb[n4 * 4];
        float4 t = o4[n4];
        float4 o;
        o.x = (t.x - mu) * rs * s4.x + b4.x;
        o.y = (t.y - mu) * rs * s4.y + b4.y;
        o.z = (t.z - mu) * rs * s4.z + b4.z;
        o.w = (t.w - mu) * rs * s4.w + b4.w;
        o4[n4] = o;
    }
}

// ============================================================================
extern "C" void kernel_launch(void* const* d_in, const int* in_sizes, int n_in,
                              void* d_out, int out_size)
{
    const float*         x     = (const float*)d_in[0];
    const unsigned char* mask  = (const unsigned char*)d_in[1];
    const float*         mem0  = (const float*)d_in[2];
    const float*         Wb    = (const float*)d_in[3];
    const float*         bb    = (const float*)d_in[4];
    const float*         Wu    = (const float*)d_in[5];
    const float*         bu    = (const float*)d_in[6];
    const float*         Wr    = (const float*)d_in[7];
    const float*         br    = (const float*)d_in[8];
    const float*         Ww    = (const float*)d_in[9];
    const float*         bw    = (const float*)d_in[10];
    const float*         dlg   = (const float*)d_in[11];
    const float*         ffw1  = (const float*)d_in[12];
    const float*         ffb1  = (const float*)d_in[13];
    const float*         ffw2  = (const float*)d_in[14];
    const float*         ffb2  = (const float*)d_in[15];
    const float*         mlns  = (const float*)d_in[16];
    const float*         mlnb  = (const float*)d_in[17];
    const float*         flns  = (const float*)d_in[18];
    const float*         flnb  = (const float*)d_in[19];
    const float*         olns  = (const float*)d_in[20];
    const float*         olnb  = (const float*)d_in[21];
    float* out = (float*)d_out;

    float *H, *Wpre, *Mem, *h1, *hid, *h2, *cA, *cB, *cM, *ps, *pss;
    cudaGetSymbolAddress((void**)&H,    g_H);
    cudaGetSymbolAddress((void**)&Wpre, g_Wpre);
    cudaGetSymbolAddress((void**)&Mem,  g_Mem);
    cudaGetSymbolAddress((void**)&h1,   g_h1);
    cudaGetSymbolAddress((void**)&hid,  g_hid);
    cudaGetSymbolAddress((void**)&h2,   g_h2);
    cudaGetSymbolAddress((void**)&cA,   g_cA);
    cudaGetSymbolAddress((void**)&cB,   g_cB);
    cudaGetSymbolAddress((void**)&cM,   g_cM);
    cudaGetSymbolAddress((void**)&ps,   g_ps);
    cudaGetSymbolAddress((void**)&pss,  g_pss);

    static bool attr_done = false;
    if (!attr_done) {
        cudaFuncSetAttribute(mma_gemm<1024,0>, cudaFuncAttributeMaxDynamicSharedMemorySize, SMEM_BYTES);
        cudaFuncSetAttribute(mma_gemm< 128,1>, cudaFuncAttributeMaxDynamicSharedMemorySize, SMEM_BYTES);
        cudaFuncSetAttribute(mma_gemm< 128,2>, cudaFuncAttributeMaxDynamicSharedMemorySize, SMEM_BYTES);
        cudaFuncSetAttribute(mma_gemm< 128,3>, cudaFuncAttributeMaxDynamicSharedMemorySize, SMEM_BYTES);
        cudaFuncSetAttribute(mma_gemm< 512,3>, cudaFuncAttributeMaxDynamicSharedMemorySize, SMEM_BYTES);
        cudaFuncSetAttribute(mma_gemm< 128,4>, cudaFuncAttributeMaxDynamicSharedMemorySize, SMEM_BYTES);
        attr_done = true;
    }

    dim3 blk(256);

    // 1) H = x @ Wb + bb                    (K=1024, N=128)
    mma_gemm<1024,0><<<dim3(1,256), blk, SMEM_BYTES>>>(x, 1024, Wb, 128, bb,
                                           nullptr, nullptr, nullptr, H, 128, nullptr, nullptr);
    // 2) Wpre = tanh(H @ Ww + bw)           (K=128, N=128)
    mma_gemm<128,1><<<dim3(1,256), blk, SMEM_BYTES>>>(H, 128, Ww, 128, bw,
                                          nullptr, nullptr, nullptr, Wpre, 128, nullptr, nullptr);
    // 3) chunked parallel scan -> Mem[t], final mem -> out tail
    scan_pass1<<<NCH*2048/256, blk>>>(Wpre, mask, dlg, cA, cB);
    scan_pass2<<<2048*32/256, blk>>>(cA, cB, mem0, cM, out + (size_t)ROWS * DM);
    scan_pass3<<<NCH*2048/256, blk>>>(Wpre, mask, dlg, cM, Mem);
    // 4) h1 = LN(H + Mem@Wr + br) * mln_s + mln_b     (K=128, N=128)
    mma_gemm<128,3><<<dim3(1,256), blk, SMEM_BYTES>>>(Mem, 128, Wr, 128, br,
                                          H, mlns, mlnb, h1, 128, nullptr, nullptr);
    // 5) hid = relu(h1 @ ff_w1 + ff_b1)     (K=128, N=512)
    mma_gemm<128,2><<<dim3(4,256), blk, SMEM_BYTES>>>(h1, 128, ffw1, 512, ffb1,
                                          nullptr, nullptr, nullptr, hid, 512, nullptr, nullptr);
    // 6) h2 = LN(h1 + hid@ff_w2 + ff_b2) * fln_s + fln_b   (K=512, N=128)
    mma_gemm<512,3><<<dim3(1,256), blk, SMEM_BYTES>>>(hid, 512, ffw2, 128, ffb2,
                                          h1, flns, flnb, h2, 128, nullptr, nullptr);
    // 7) out <- v = x + h2@Wu + bu; partial row stats -> ps/pss   (N=1024)
    mma_gemm<128,4><<<dim3(8,256), blk, SMEM_BYTES>>>(h2, 128, Wu, 1024, bu,
                                          x, nullptr, nullptr, out, 1024, ps, pss);
    // 8) out = LN(v) * oln_s + oln_b  (in place)
    norm_kernel<<<ROWS/8, blk>>>(ps, pss, olns, olnb, out);

    (void)in_sizes; (void)n_in; (void)out_size;
}

// round 14
// speedup vs baseline: 3.2614x; 1.0010x over previous
#include <cuda_runtime.h>
#include <math.h>
#include <stdint.h>

#define T_STEPS 2048
#define BATCH   16
#define DM      1024
#define DB      128
#define DH      512
#define ROWS    (T_STEPS*BATCH)   /* 32768 */
#define EPSLN   1e-5f
#define CH      64                /* scan chunk length */
#define NCH     (T_STEPS/CH)      /* 32 chunks -> one warp per lane */

// ---------------- scratch (no allocations allowed; static device globals) ---
__device__ float g_H[ROWS*DB];      // fp32 (residual for GEMM4)
__device__ float g_Htf[ROWS*DB];    // tf32 copy (A of GEMM2)
__device__ float g_Wpre[ROWS*DB];
__device__ float g_Mem[ROWS*DB];    // tf32-rounded (A of GEMM4)
__device__ float g_h1[ROWS*DB];     // fp32 (residual for GEMM6)
__device__ float g_h1tf[ROWS*DB];   // tf32 copy (A of GEMM5)
__device__ float g_hid[ROWS*DH];    // tf32-rounded (A of GEMM6)
__device__ float g_h2[ROWS*DB];     // tf32-rounded (A of GEMM7)
__device__ float g_cA[NCH*2048];
__device__ float g_cB[NCH*2048];
__device__ float g_cM[NCH*2048];
__device__ float g_ps [ROWS*8];
__device__ float g_pss[ROWS*8];
// tf32-preconverted weights
__device__ float g_Wbt[DM*DB];
__device__ float g_Wwt[DB*DB];
__device__ float g_Wrt[DB*DB];
__device__ float g_w1t[DB*DH];
__device__ float g_w2t[DH*DB];
__device__ float g_Wut[DB*DM];

// ---------------------------------------------------------------------------
__device__ __forceinline__ uint32_t f2tf32(float f) {
    uint32_t r;
    asm("cvt.rna.tf32.f32 %0, %1;" : "=r"(r) : "f"(f));
    return r;
}
__device__ __forceinline__ float tf32f(float f) {
    return __uint_as_float(f2tf32(f));
}
__device__ __forceinline__ void mma8(float& d0, float& d1, float& d2, float& d3,
                                     uint32_t a0, uint32_t a1, uint32_t a2, uint32_t a3,
                                     uint32_t b0, uint32_t b1)
{
    asm volatile(
        "mma.sync.aligned.m16n8k8.row.col.f32.tf32.tf32.f32 "
        "{%0,%1,%2,%3}, {%4,%5,%6,%7}, {%8,%9}, {%0,%1,%2,%3};"
        : "+f"(d0), "+f"(d1), "+f"(d2), "+f"(d3)
        : "r"(a0), "r"(a1), "r"(a2), "r"(a3), "r"(b0), "r"(b1));
}
__device__ __forceinline__ void cp_async16(void* smem_dst, const void* gsrc) {
    uint32_t d = (uint32_t)__cvta_generic_to_shared(smem_dst);
    asm volatile("cp.async.cg.shared.global [%0], [%1], 16;\n" :: "r"(d), "l"(gsrc));
}
__device__ __forceinline__ void cp_commit() {
    asm volatile("cp.async.commit_group;\n" ::: "memory");
}
template<int N> __device__ __forceinline__ void cp_wait() {
    asm volatile("cp.async.wait_group %0;\n" :: "n"(N) : "memory");
}

#define AS_STRIDE 36
#define BS_STRIDE 136
#define AS_BUF (128*AS_STRIDE)
#define BS_BUF (32*BS_STRIDE)
#define SMEM_FLOATS (2*AS_BUF + 2*BS_BUF + 2*512)
#define SMEM_BYTES  (SMEM_FLOATS*4)

// ============================================================================
// tf32 tensor-core GEMM, cp.async double-buffered. Block 128x128x32,
// 8 warps (2m x 4n), warp tile 64x32, mma m16n8k8.
// CONVA: convert A smem values fp32->tf32 at fragment load (only GEMM1).
// B must be pre-converted tf32 bits. When !CONVA, A must be too.
// ROUNDC: round C stores to tf32 (when C feeds a later GEMM as A).
// EPI: 0 = +bias (optional tf32 twin store to Ctf),
//      1 = +bias,tanh, 2 = +bias,relu,
//      3 = +bias,+res(128-stride), row-LN over 128 (n0==0; optional Ctf twin)
//      4 = +bias,+res(ldc), write v, emit partial s/ss for deferred LN
// ============================================================================
template<int KTOT, int EPI, bool CONVA, bool ROUNDC>
__global__ void __launch_bounds__(256, 2)
mma_gemm(const float* __restrict__ A, int lda,
         const float* __restrict__ Bw, int ldb,
         const float* __restrict__ bias,
         const float* __restrict__ res,
         const float* __restrict__ ln_s, const float* __restrict__ ln_b,
         float* __restrict__ C, int ldc,
         float* __restrict__ Ctf,
         float* __restrict__ ps, float* __restrict__ pss)
{
    extern __shared__ float dynsm[];
    float* Asm   = dynsm;                       // [2][128][36]
    float* Bsm   = dynsm + 2*AS_BUF;            // [2][32][136]
    float* red_s  = Bsm + 2*BS_BUF;             // [4][128]
    float* red_ss = red_s + 512;                // [4][128]

    const int tid  = threadIdx.x;
    const int lane = tid & 31;
    const int wid  = tid >> 5;
    const int g    = lane >> 2;         // 0..7
    const int t    = lane & 3;          // 0..3
    const int wm   = (wid >> 2) * 64;
    const int wcol = wid & 3;
    const int wn   = wcol * 32;
    const int m0   = blockIdx.y * 128;
    const int n0   = blockIdx.x * 128;

    constexpr int NT = KTOT / 32;

    float acc[4][4][4];
#pragma unroll
    for (int mi = 0; mi < 4; mi++)
#pragma unroll
        for (int ni = 0; ni < 4; ni++)
#pragma unroll
            for (int r = 0; r < 4; r++) acc[mi][ni][r] = 0.f;

    const int a_m  = tid >> 3;
    const int a_kv = tid & 7;
    const int b_k  = tid >> 5;
    const int b_nv = tid & 31;

    auto load_tile = [&](int kt, int buf) {
        const int k0 = kt * 32;
        float* Ab = Asm + buf * AS_BUF;
        float* Bb = Bsm + buf * BS_BUF;
#pragma unroll
        for (int it = 0; it < 4; ++it) {
            int m = a_m + it * 32;
            cp_async16(&Ab[m * AS_STRIDE + a_kv * 4],
                       &A[(size_t)(m0 + m) * lda + k0 + a_kv * 4]);
        }
#pragma unroll
        for (int it = 0; it < 4; ++it) {
            int k = b_k + it * 8;
            cp_async16(&Bb[k * BS_STRIDE + b_nv * 4],
                       &Bw[(size_t)(k0 + k) * ldb + n0 + b_nv * 4]);
        }
    };

    load_tile(0, 0);
    cp_commit();

    for (int kt = 0; kt < NT; ++kt) {
        if (kt + 1 < NT) {
            load_tile(kt + 1, (kt + 1) & 1);
            cp_commit();
            cp_wait<1>();
        } else {
            cp_wait<0>();
        }
        __syncthreads();

        const float* Ab = Asm + (kt & 1) * AS_BUF;
        const float* Bb = Bsm + (kt & 1) * BS_BUF;
#pragma unroll
        for (int kk = 0; kk < 4; kk++) {
            uint32_t av[4][4];
#pragma unroll
            for (int mi = 0; mi < 4; mi++) {
                int r0 = wm + mi * 16 + g;
                if (CONVA) {
                    av[mi][0] = f2tf32(Ab[ r0      * AS_STRIDE + kk*8 + t    ]);
                    av[mi][1] = f2tf32(Ab[(r0 + 8) * AS_STRIDE + kk*8 + t    ]);
                    av[mi][2] = f2tf32(Ab[ r0      * AS_STRIDE + kk*8 + t + 4]);
                    av[mi][3] = f2tf32(Ab[(r0 + 8) * AS_STRIDE + kk*8 + t + 4]);
                } else {
                    av[mi][0] = __float_as_uint(Ab[ r0      * AS_STRIDE + kk*8 + t    ]);
                    av[mi][1] = __float_as_uint(Ab[(r0 + 8) * AS_STRIDE + kk*8 + t    ]);
                    av[mi][2] = __float_as_uint(Ab[ r0      * AS_STRIDE + kk*8 + t + 4]);
                    av[mi][3] = __float_as_uint(Ab[(r0 + 8) * AS_STRIDE + kk*8 + t + 4]);
                }
            }
            uint32_t bv[4][2];
#pragma unroll
            for (int ni = 0; ni < 4; ni++) {
                bv[ni][0] = __float_as_uint(Bb[(kk*8 + t    ) * BS_STRIDE + wn + ni*8 + g]);
                bv[ni][1] = __float_as_uint(Bb[(kk*8 + t + 4) * BS_STRIDE + wn + ni*8 + g]);
            }
#pragma unroll
            for (int mi = 0; mi < 4; mi++)
#pragma unroll
                for (int ni = 0; ni < 4; ni++)
                    mma8(acc[mi][ni][0], acc[mi][ni][1], acc[mi][ni][2], acc[mi][ni][3],
                         av[mi][0], av[mi][1], av[mi][2], av[mi][3],
                         bv[ni][0], bv[ni][1]);
        }
        __syncthreads();
    }

    // ---- epilogue ----------------------------------------------------------
    float2 bias2[4];
#pragma unroll
    for (int ni = 0; ni < 4; ni++)
        bias2[ni] = *(const float2*)&bias[n0 + wn + ni*8 + 2*t];

    if (EPI == 0 || EPI == 1 || EPI == 2) {
#pragma unroll
        for (int mi = 0; mi < 4; mi++) {
            size_t r0 = (size_t)(m0 + wm + mi*16 + g);
            size_t r1 = r0 + 8;
#pragma unroll
            for (int ni = 0; ni < 4; ni++) {
                int c = n0 + wn + ni*8 + 2*t;
                float v0 = acc[mi][ni][0] + bias2[ni].x;
                float v1 = acc[mi][ni][1] + bias2[ni].y;
                float v2 = acc[mi][ni][2] + bias2[ni].x;
                float v3 = acc[mi][ni][3] + bias2[ni].y;
                if (EPI == 1) { v0 = tanhf(v0); v1 = tanhf(v1); v2 = tanhf(v2); v3 = tanhf(v3); }
                if (EPI == 2) {
                    v0 = fmaxf(v0, 0.f); v1 = fmaxf(v1, 0.f);
                    v2 = fmaxf(v2, 0.f); v3 = fmaxf(v3, 0.f);
                }
                float s0 = ROUNDC ? tf32f(v0) : v0;
                float s1 = ROUNDC ? tf32f(v1) : v1;
                float s2 = ROUNDC ? tf32f(v2) : v2;
                float s3 = ROUNDC ? tf32f(v3) : v3;
                *(float2*)&C[r0 * ldc + c] = make_float2(s0, s1);
                *(float2*)&C[r1 * ldc + c] = make_float2(s2, s3);
                if (Ctf) {
                    *(float2*)&Ctf[r0 * ldc + c] = make_float2(tf32f(v0), tf32f(v1));
                    *(float2*)&Ctf[r1 * ldc + c] = make_float2(tf32f(v2), tf32f(v3));
                }
            }
        }
    } else if (EPI == 4) {
#pragma unroll
        for (int mi = 0; mi < 4; mi++) {
            size_t r0 = (size_t)(m0 + wm + mi*16 + g);
            size_t r1 = r0 + 8;
#pragma unroll
            for (int ni = 0; ni < 4; ni++) {
                int c = n0 + wn + ni*8 + 2*t;
                float2 rv0 = *(const float2*)&res[r0 * ldc + c];
                float2 rv1 = *(const float2*)&res[r1 * ldc + c];
                acc[mi][ni][0] += bias2[ni].x + rv0.x;
                acc[mi][ni][1] += bias2[ni].y + rv0.y;
                acc[mi][ni][2] += bias2[ni].x + rv1.x;
                acc[mi][ni][3] += bias2[ni].y + rv1.y;
                *(float2*)&C[r0 * ldc + c] = make_float2(acc[mi][ni][0], acc[mi][ni][1]);
                *(float2*)&C[r1 * ldc + c] = make_float2(acc[mi][ni][2], acc[mi][ni][3]);
            }
        }
#pragma unroll
        for (int mi = 0; mi < 4; mi++) {
            float s0 = 0.f, ss0 = 0.f, s1 = 0.f, ss1 = 0.f;
#pragma unroll
            for (int ni = 0; ni < 4; ni++) {
                float a0 = acc[mi][ni][0], a1 = acc[mi][ni][1];
                float a2 = acc[mi][ni][2], a3 = acc[mi][ni][3];
                s0 += a0 + a1;  ss0 += a0*a0 + a1*a1;
                s1 += a2 + a3;  ss1 += a2*a2 + a3*a3;
            }
#pragma unroll
            for (int o = 1; o <= 2; o <<= 1) {
                s0  += __shfl_xor_sync(0xffffffffu, s0,  o);
                ss0 += __shfl_xor_sync(0xffffffffu, ss0, o);
                s1  += __shfl_xor_sync(0xffffffffu, s1,  o);
                ss1 += __shfl_xor_sync(0xffffffffu, ss1, o);
            }
            if (t == 0) {
                int rb0 = wm + mi*16 + g;
                red_s [wcol*128 + rb0]     = s0;  red_ss[wcol*128 + rb0]     = ss0;
                red_s [wcol*128 + rb0 + 8] = s1;  red_ss[wcol*128 + rb0 + 8] = ss1;
            }
        }
        __syncthreads();
        if (tid < 128) {
            float S  = red_s [tid] + red_s [128+tid] + red_s [256+tid] + red_s [384+tid];
            float SS = red_ss[tid] + red_ss[128+tid] + red_ss[256+tid] + red_ss[384+tid];
            size_t row = (size_t)(m0 + tid);
            ps [row * 8 + blockIdx.x] = S;
            pss[row * 8 + blockIdx.x] = SS;
        }
    } else {    // EPI == 3
#pragma unroll
        for (int mi = 0; mi < 4; mi++) {
            size_t r0 = (size_t)(m0 + wm + mi*16 + g);
            size_t r1 = r0 + 8;
#pragma unroll
            for (int ni = 0; ni < 4; ni++) {
                int c = wn + ni*8 + 2*t;
                float2 rv0 = *(const float2*)&res[r0 * 128 + c];
                float2 rv1 = *(const float2*)&res[r1 * 128 + c];
                acc[mi][ni][0] += bias2[ni].x + rv0.x;
                acc[mi][ni][1] += bias2[ni].y + rv0.y;
                acc[mi][ni][2] += bias2[ni].x + rv1.x;
                acc[mi][ni][3] += bias2[ni].y + rv1.y;
            }
        }
#pragma unroll
        for (int mi = 0; mi < 4; mi++) {
            float s0 = 0.f, ss0 = 0.f, s1 = 0.f, ss1 = 0.f;
#pragma unroll
            for (int ni = 0; ni < 4; ni++) {
                float a0 = acc[mi][ni][0], a1 = acc[mi][ni][1];
                float a2 = acc[mi][ni][2], a3 = acc[mi][ni][3];
                s0 += a0 + a1;  ss0 += a0*a0 + a1*a1;
                s1 += a2 + a3;  ss1 += a2*a2 + a3*a3;
            }
#pragma unroll
            for (int o = 1; o <= 2; o <<= 1) {
                s0  += __shfl_xor_sync(0xffffffffu, s0,  o);
                ss0 += __shfl_xor_sync(0xffffffffu, ss0, o);
                s1  += __shfl_xor_sync(0xffffffffu, s1,  o);
                ss1 += __shfl_xor_sync(0xffffffffu, ss1, o);
            }
            if (t == 0) {
                int rb0 = wm + mi*16 + g;
                red_s [wcol*128 + rb0]     = s0;  red_ss[wcol*128 + rb0]     = ss0;
                red_s [wcol*128 + rb0 + 8] = s1;  red_ss[wcol*128 + rb0 + 8] = ss1;
            }
        }
        __syncthreads();

        float2 ls2[4], lb2[4];
#pragma unroll
        for (int ni = 0; ni < 4; ni++) {
            ls2[ni] = *(const float2*)&ln_s[wn + ni*8 + 2*t];
            lb2[ni] = *(const float2*)&ln_b[wn + ni*8 + 2*t];
        }
#pragma unroll
        for (int mi = 0; mi < 4; mi++) {
            int rb0 = wm + mi*16 + g;
            int rb1 = rb0 + 8;
            float S0  = red_s [rb0] + red_s [128+rb0] + red_s [256+rb0] + red_s [384+rb0];
            float SS0 = red_ss[rb0] + red_ss[128+rb0] + red_ss[256+rb0] + red_ss[384+rb0];
            float S1  = red_s [rb1] + red_s [128+rb1] + red_s [256+rb1] + red_s [384+rb1];
            float SS1 = red_ss[rb1] + red_ss[128+rb1] + red_ss[256+rb1] + red_ss[384+rb1];
            float mu0 = S0 * (1.f/128.f);
            float mu1 = S1 * (1.f/128.f);
            float rs0 = rsqrtf(SS0 * (1.f/128.f) - mu0*mu0 + EPSLN);
            float rs1 = rsqrtf(SS1 * (1.f/128.f) - mu1*mu1 + EPSLN);
            size_t r0 = (size_t)(m0 + rb0);
            size_t r1 = (size_t)(m0 + rb1);
#pragma unroll
            for (int ni = 0; ni < 4; ni++) {
                int c = wn + ni*8 + 2*t;
                float o0 = (acc[mi][ni][0] - mu0) * rs0 * ls2[ni].x + lb2[ni].x;
                float o1 = (acc[mi][ni][1] - mu0) * rs0 * ls2[ni].y + lb2[ni].y;
                float o2 = (acc[mi][ni][2] - mu1) * rs1 * ls2[ni].x + lb2[ni].x;
                float o3 = (acc[mi][ni][3] - mu1) * rs1 * ls2[ni].y + lb2[ni].y;
                float p0 = ROUNDC ? tf32f(o0) : o0;
                float p1 = ROUNDC ? tf32f(o1) : o1;
                float p2 = ROUNDC ? tf32f(o2) : o2;
                float p3 = ROUNDC ? tf32f(o3) : o3;
                *(float2*)&C[r0 * ldc + c] = make_float2(p0, p1);
                *(float2*)&C[r1 * ldc + c] = make_float2(p2, p3);
                if (Ctf) {
                    *(float2*)&Ctf[r0 * ldc + c] = make_float2(tf32f(o0), tf32f(o1));
                    *(float2*)&Ctf[r1 * ldc + c] = make_float2(tf32f(o2), tf32f(o3));
                }
            }
        }
    }
}

// ============================================================================
// One-shot weight conversion fp32 -> tf32 bit pattern.
// ============================================================================
#define S1 (DM*DB)
#define S2 (S1 + DB*DB)
#define S3 (S2 + DB*DB)
#define S4 (S3 + DB*DH)
#define S5 (S4 + DH*DB)
#define S6 (S5 + DB*DM)
__global__ void __launch_bounds__(256)
cvt_weights(const float* __restrict__ Wb, const float* __restrict__ Ww,
            const float* __restrict__ Wr, const float* __restrict__ w1,
            const float* __restrict__ w2, const float* __restrict__ Wu,
            float* __restrict__ o1, float* __restrict__ o2,
            float* __restrict__ o3, float* __restrict__ o4,
            float* __restrict__ o5, float* __restrict__ o6)
{
    int i = blockIdx.x * blockDim.x + threadIdx.x;
    if      (i < S1) o1[i]      = tf32f(Wb[i]);
    else if (i < S2) o2[i - S1] = tf32f(Ww[i - S1]);
    else if (i < S3) o3[i - S2] = tf32f(Wr[i - S2]);
    else if (i < S4) o4[i - S3] = tf32f(w1[i - S3]);
    else if (i < S5) o5[i - S4] = tf32f(w2[i - S4]);
    else if (i < S6) o6[i - S5] = tf32f(Wu[i - S5]);
}

// ============================================================================
// Chunked parallel scan of  m' = a*m + b,  a = mask?1:dec, b = mask?0:omd*w.
// ============================================================================
__global__ void __launch_bounds__(256)
scan_pass1(const float* __restrict__ Wpre,
           const unsigned char* __restrict__ mask,
           const float* __restrict__ decay_logit,
           float* __restrict__ cA, float* __restrict__ cB)
{
    int idx = blockIdx.x * blockDim.x + threadIdx.x;
    int i = idx & 2047;
    int c = idx >> 11;
    int b = i >> 7;
    float dec = 1.f / (1.f + expf(-decay_logit[i & 127]));
    float omd = 1.f - dec;
    float Aa = 1.f, Bb = 0.f;
#pragma unroll 4
    for (int s = 0; s < CH; s++) {
        int t = c * CH + s;
        bool mk = mask[t * BATCH + b];
        float w  = Wpre[(size_t)t * 2048 + i];
        float a  = mk ? 1.f : dec;
        float bt = mk ? 0.f : omd * w;
        Aa = a * Aa;
        Bb = a * Bb + bt;
    }
    cA[c * 2048 + i] = Aa;
    cB[c * 2048 + i] = Bb;
}

__global__ void __launch_bounds__(256)
scan_pass2(const float* __restrict__ cA, const float* __restrict__ cB,
           const float* __restrict__ mem0,
           float* __restrict__ cM, float* __restrict__ out_final)
{
    int gt = blockIdx.x * blockDim.x + threadIdx.x;
    int i  = gt >> 5;
    int c  = gt & 31;
    float A = cA[c * 2048 + i];
    float B = cB[c * 2048 + i];
#pragma unroll
    for (int o = 1; o < 32; o <<= 1) {
        float Ap = __shfl_up_sync(0xffffffffu, A, o);
        float Bp = __shfl_up_sync(0xffffffffu, B, o);
        if (c >= o) { B = A * Bp + B; A = A * Ap; }
    }
    float Ae = __shfl_up_sync(0xffffffffu, A, 1);
    float Be = __shfl_up_sync(0xffffffffu, B, 1);
    if (c == 0) { Ae = 1.f; Be = 0.f; }
    float m0v = mem0[i];
    cM[c * 2048 + i] = Ae * m0v + Be;
    if (c == 31) out_final[i] = A * m0v + B;
}

// Writes Mem tf32-rounded (it is only ever consumed as a GEMM A-operand).
__global__ void __launch_bounds__(256)
scan_pass3(const float* __restrict__ Wpre,
           const unsigned char* __restrict__ mask,
           const float* __restrict__ decay_logit,
           const float* __restrict__ cM,
           float* __restrict__ Mem)
{
    int idx = blockIdx.x * blockDim.x + threadIdx.x;
    int i = idx & 2047;
    int c = idx >> 11;
    int b = i >> 7;
    float dec = 1.f / (1.f + expf(-decay_logit[i & 127]));
    float omd = 1.f - dec;
    float m = cM[c * 2048 + i];
#pragma unroll 4
    for (int s = 0; s < CH; s++) {
        int t = c * CH + s;
        Mem[(size_t)t * 2048 + i] = tf32f(m);
        bool mk = mask[t * BATCH + b];
        float w  = Wpre[(size_t)t * 2048 + i];
        float nm = dec * m + omd * w;
        m = mk ? m : nm;
    }
}

// ============================================================================
// Deferred output LayerNorm.
// ============================================================================
__global__ void __launch_bounds__(256)
norm_kernel(const float* __restrict__ ps, const float* __restrict__ pss,
            const float* __restrict__ lns, const float* __restrict__ lnb,
            float* __restrict__ out)
{
    const int lane = threadIdx.x & 31;
    const int w    = threadIdx.x >> 5;
    const size_t r = (size_t)blockIdx.x * 8 + w;

    float s  = (lane < 8) ? ps [r * 8 + lane] : 0.f;
    float ss = (lane < 8) ? pss[r * 8 + lane] : 0.f;
#pragma unroll
    for (int o = 4; o > 0; o >>= 1) {
        s  += __shfl_xor_sync(0xffffffffu, s,  o);
        ss += __shfl_xor_sync(0xffffffffu, ss, o);
    }
    s  = __shfl_sync(0xffffffffu, s,  0);
    ss = __shfl_sync(0xffffffffu, ss, 0);
    float mu = s * (1.f/1024.f);
    float rs = rsqrtf(ss * (1.f/1024.f) - mu*mu + EPSLN);

    float4* o4 = (float4*)(out + r * 1024);
#pragma unroll
    for (int c = 0; c < 8; c++) {
        int n4 = c * 32 + lane;
        float4 s4 = *(const float4*)&lns[n4 * 4];
        float4 b4 = *(const float4*)&lnb[n4 * 4];
        float4 t = o4[n4];
        float4 o;
        o.x = (t.x - mu) * rs * s4.x + b4.x;
        o.y = (t.y - mu) * rs * s4.y + b4.y;
        o.z = (t.z - mu) * rs * s4.z + b4.z;
        o.w = (t.w - mu) * rs * s4.w + b4.w;
        o4[n4] = o;
    }
}

// ============================================================================
extern "C" void kernel_launch(void* const* d_in, const int* in_sizes, int n_in,
                              void* d_out, int out_size)
{
    const float*         x     = (const float*)d_in[0];
    const unsigned char* mask  = (const unsigned char*)d_in[1];
    const float*         mem0  = (const float*)d_in[2];
    const float*         Wb    = (const float*)d_in[3];
    const float*         bb    = (const float*)d_in[4];
    const float*         Wu    = (const float*)d_in[5];
    const float*         bu    = (const float*)d_in[6];
    const float*         Wr    = (const float*)d_in[7];
    const float*         br    = (const float*)d_in[8];
    const float*         Ww    = (const float*)d_in[9];
    const float*         bw    = (const float*)d_in[10];
    const float*         dlg   = (const float*)d_in[11];
    const float*         ffw1  = (const float*)d_in[12];
    const float*         ffb1  = (const float*)d_in[13];
    const float*         ffw2  = (const float*)d_in[14];
    const float*         ffb2  = (const float*)d_in[15];
    const float*         mlns  = (const float*)d_in[16];
    const float*         mlnb  = (const float*)d_in[17];
    const float*         flns  = (const float*)d_in[18];
    const float*         flnb  = (const float*)d_in[19];
    const float*         olns  = (const float*)d_in[20];
    const float*         olnb  = (const float*)d_in[21];
    float* out = (float*)d_out;

    float *H, *Htf, *Wpre, *Mem, *h1, *h1tf, *hid, *h2, *cA, *cB, *cM, *ps, *pss;
    float *Wbt, *Wwt, *Wrt, *w1t, *w2t, *Wut;
    cudaGetSymbolAddress((void**)&H,    g_H);
    cudaGetSymbolAddress((void**)&Htf,  g_Htf);
    cudaGetSymbolAddress((void**)&Wpre, g_Wpre);
    cudaGetSymbolAddress((void**)&Mem,  g_Mem);
    cudaGetSymbolAddress((void**)&h1,   g_h1);
    cudaGetSymbolAddress((void**)&h1tf, g_h1tf);
    cudaGetSymbolAddress((void**)&hid,  g_hid);
    cudaGetSymbolAddress((void**)&h2,   g_h2);
    cudaGetSymbolAddress((void**)&cA,   g_cA);
    cudaGetSymbolAddress((void**)&cB,   g_cB);
    cudaGetSymbolAddress((void**)&cM,   g_cM);
    cudaGetSymbolAddress((void**)&ps,   g_ps);
    cudaGetSymbolAddress((void**)&pss,  g_pss);
    cudaGetSymbolAddress((void**)&Wbt,  g_Wbt);
    cudaGetSymbolAddress((void**)&Wwt,  g_Wwt);
    cudaGetSymbolAddress((void**)&Wrt,  g_Wrt);
    cudaGetSymbolAddress((void**)&w1t,  g_w1t);
    cudaGetSymbolAddress((void**)&w2t,  g_w2t);
    cudaGetSymbolAddress((void**)&Wut,  g_Wut);

    static bool attr_done = false;
    if (!attr_done) {
        cudaFuncSetAttribute(mma_gemm<1024,0,true ,false>, cudaFuncAttributeMaxDynamicSharedMemorySize, SMEM_BYTES);
        cudaFuncSetAttribute(mma_gemm< 128,1,false,false>, cudaFuncAttributeMaxDynamicSharedMemorySize, SMEM_BYTES);
        cudaFuncSetAttribute(mma_gemm< 128,2,false,true >, cudaFuncAttributeMaxDynamicSharedMemorySize, SMEM_BYTES);
        cudaFuncSetAttribute(mma_gemm< 128,3,false,false>, cudaFuncAttributeMaxDynamicSharedMemorySize, SMEM_BYTES);
        cudaFuncSetAttribute(mma_gemm< 512,3,false,true >, cudaFuncAttributeMaxDynamicSharedMemorySize, SMEM_BYTES);
        cudaFuncSetAttribute(mma_gemm< 128,4,false,false>, cudaFuncAttributeMaxDynamicSharedMemorySize, SMEM_BYTES);
        attr_done = true;
    }

    dim3 blk(256);

    // 0) pre-convert all weights to tf32 bit patterns
    cvt_weights<<<(S6 + 255)/256, blk>>>(Wb, Ww, Wr, ffw1, ffw2, Wu,
                                         Wbt, Wwt, Wrt, w1t, w2t, Wut);
    // 1) H = x @ Wb + bb  (A converted in-loop; twin tf32 copy -> Htf)
    mma_gemm<1024,0,true,false><<<dim3(1,256), blk, SMEM_BYTES>>>(
        x, 1024, Wbt, 128, bb, nullptr, nullptr, nullptr, H, 128, Htf, nullptr, nullptr);
    // 2) Wpre = tanh(Htf @ Ww + bw)   (fp32 out, feeds scan)
    mma_gemm<128,1,false,false><<<dim3(1,256), blk, SMEM_BYTES>>>(
        Htf, 128, Wwt, 128, bw, nullptr, nullptr, nullptr, Wpre, 128, nullptr, nullptr, nullptr);
    // 3) chunked parallel scan -> Mem[t] (tf32-rounded), final mem -> out tail
    scan_pass1<<<NCH*2048/256, blk>>>(Wpre, mask, dlg, cA, cB);
    scan_pass2<<<2048*32/256, blk>>>(cA, cB, mem0, cM, out + (size_t)ROWS * DM);
    scan_pass3<<<NCH*2048/256, blk>>>(Wpre, mask, dlg, cM, Mem);
    // 4) h1 = LN(H + Mem@Wr + br)  (fp32 h1 for residual; twin tf32 -> h1tf)
    mma_gemm<128,3,false,false><<<dim3(1,256), blk, SMEM_BYTES>>>(
        Mem, 128, Wrt, 128, br, H, mlns, mlnb, h1, 128, h1tf, nullptr, nullptr);
    // 5) hid = relu(h1tf @ ff_w1 + ff_b1)   (tf32-rounded out)
    mma_gemm<128,2,false,true><<<dim3(4,256), blk, SMEM_BYTES>>>(
        h1tf, 128, w1t, 512, ffb1, nullptr, nullptr, nullptr, hid, 512, nullptr, nullptr, nullptr);
    // 6) h2 = LN(h1 + hid@ff_w2 + ff_b2)    (tf32-rounded out)
    mma_gemm<512,3,false,true><<<dim3(1,256), blk, SMEM_BYTES>>>(
        hid, 512, w2t, 128, ffb2, h1, flns, flnb, h2, 128, nullptr, nullptr, nullptr);
    // 7) out <- v = x + h2@Wu + bu; partial row stats -> ps/pss
    mma_gemm<128,4,false,false><<<dim3(8,256), blk, SMEM_BYTES>>>(
        h2, 128, Wut, 1024, bu, x, nullptr, nullptr, out, 1024, nullptr, ps, pss);
    // 8) out = LN(v) * oln_s + oln_b  (in place)
    norm_kernel<<<ROWS/8, blk>>>(ps, pss, olns, olnb, out);

    (void)in_sizes; (void)n_in; (void)out_size;
}